// round 1
// baseline (speedup 1.0000x reference)
#include <cuda_runtime.h>
#include <math.h>

// Problem constants (fixed by setup_inputs)
#define BB    2
#define HH    16
#define NSEQ  2048
#define EE    1024
#define DD    64
#define CHK   128
#define NCK   16            // NSEQ / CHK
#define MROWS 4096          // BB * NSEQ
#define EPSV  1e-6f

// ---------------- scratch (device globals; no allocation allowed) ----------
__device__ float g_q[BB*HH*NSEQ*DD];     // 16 MB, (B,H,N,D)
__device__ float g_k[BB*HH*NSEQ*DD];
__device__ float g_v[BB*HH*NSEQ*DD];
__device__ float g_attn[BB*NSEQ*EE];     // attention out in (B,N,E)
__device__ float g_S[BB*HH*NCK*DD*DD];   // per-chunk K^T V (prefixed in-place)
__device__ float g_z[BB*HH*NCK*DD];      // per-chunk K colsum (prefixed)

// ---------------------------------------------------------------------------
// NT GEMM: C[m,n] = sum_k A[m,k] * W[n,k];  M=4096, N=1024, K=1024.
// FMAP: apply elu(x)+1 in epilogue.  BHND: scatter into (B,H,N,D) layout.
// ---------------------------------------------------------------------------
template<bool FMAP, bool BHND>
__global__ void __launch_bounds__(256) gemm_nt(const float* __restrict__ A,
                                               const float* __restrict__ W,
                                               float* __restrict__ C) {
    __shared__ float As[16][132];   // [k][m], padded
    __shared__ float Bs[16][132];   // [k][n], padded
    const int tid = threadIdx.x;
    const int tx = tid & 15, ty = tid >> 4;
    const int bm = blockIdx.y * 128, bn = blockIdx.x * 128;

    float acc[8][8];
#pragma unroll
    for (int i = 0; i < 8; i++)
#pragma unroll
        for (int j = 0; j < 8; j++) acc[i][j] = 0.f;

    for (int k0 = 0; k0 < 1024; k0 += 16) {
#pragma unroll
        for (int it = 0; it < 2; it++) {
            int i  = tid + it * 256;       // [0,512)
            int r  = i >> 2;
            int c4 = (i & 3) << 2;
            float4 va = *(const float4*)(A + (size_t)(bm + r) * 1024 + k0 + c4);
            As[c4 + 0][r] = va.x; As[c4 + 1][r] = va.y;
            As[c4 + 2][r] = va.z; As[c4 + 3][r] = va.w;
            float4 vb = *(const float4*)(W + (size_t)(bn + r) * 1024 + k0 + c4);
            Bs[c4 + 0][r] = vb.x; Bs[c4 + 1][r] = vb.y;
            Bs[c4 + 2][r] = vb.z; Bs[c4 + 3][r] = vb.w;
        }
        __syncthreads();
#pragma unroll
        for (int kk = 0; kk < 16; kk++) {
            float4 a0 = *(const float4*)&As[kk][ty * 8];
            float4 a1 = *(const float4*)&As[kk][ty * 8 + 4];
            float4 b0 = *(const float4*)&Bs[kk][tx * 8];
            float4 b1 = *(const float4*)&Bs[kk][tx * 8 + 4];
            float a[8] = {a0.x, a0.y, a0.z, a0.w, a1.x, a1.y, a1.z, a1.w};
            float b[8] = {b0.x, b0.y, b0.z, b0.w, b1.x, b1.y, b1.z, b1.w};
#pragma unroll
            for (int i = 0; i < 8; i++)
#pragma unroll
                for (int j = 0; j < 8; j++) acc[i][j] += a[i] * b[j];
        }
        __syncthreads();
    }

#pragma unroll
    for (int i = 0; i < 8; i++) {
        int row = bm + ty * 8 + i;
#pragma unroll
        for (int j = 0; j < 8; j++) {
            int col = bn + tx * 8 + j;
            float v = acc[i][j];
            if (FMAP) v = (v > 0.f) ? (v + 1.f) : expf(v);
            size_t idx;
            if (BHND) {
                int b = row >> 11, n = row & 2047;
                int h = col >> 6,  d = col & 63;
                idx = ((((size_t)b * HH + h) * NSEQ + n) * DD + d);
            } else {
                idx = (size_t)row * 1024 + col;
            }
            C[idx] = v;
        }
    }
}

// ---------------------------------------------------------------------------
// Pass 1: per-chunk S_c[d][v] = sum_i k[i,d]*v[i,v], z_c[d] = sum_i k[i,d]
// grid = BB*HH*NCK = 512, block = 256; dyn smem = 64 KB
// ---------------------------------------------------------------------------
__global__ void __launch_bounds__(256) chunk_kv(const float* __restrict__ k,
                                                const float* __restrict__ v,
                                                float* __restrict__ S,
                                                float* __restrict__ z) {
    extern __shared__ float sm[];
    float* ks = sm;          // 128*64
    float* vs = sm + 8192;   // 128*64
    const int blk = blockIdx.x;
    const int c = blk & 15, bh = blk >> 4;
    const size_t base = ((size_t)bh * NSEQ + (size_t)c * CHK) * DD;
    const float4* k4 = (const float4*)(k + base);
    const float4* v4 = (const float4*)(v + base);
    for (int i = threadIdx.x; i < 2048; i += 256) {
        ((float4*)ks)[i] = k4[i];
        ((float4*)vs)[i] = v4[i];
    }
    __syncthreads();

    const int dg = threadIdx.x >> 4, vg = threadIdx.x & 15;
    float acc[4][4] = {};
    float zacc[4]  = {};
    for (int i = 0; i < 128; i++) {
        float4 kv = *(const float4*)&ks[i * 64 + dg * 4];
        float4 vv = *(const float4*)&vs[i * 64 + vg * 4];
        float kr[4] = {kv.x, kv.y, kv.z, kv.w};
        float vc[4] = {vv.x, vv.y, vv.z, vv.w};
#pragma unroll
        for (int r = 0; r < 4; r++) {
            zacc[r] += kr[r];
#pragma unroll
            for (int cc = 0; cc < 4; cc++) acc[r][cc] += kr[r] * vc[cc];
        }
    }
    const size_t sb = (size_t)blk * 4096;
#pragma unroll
    for (int r = 0; r < 4; r++)
#pragma unroll
        for (int cc = 0; cc < 4; cc++)
            S[sb + (size_t)(dg * 4 + r) * 64 + vg * 4 + cc] = acc[r][cc];
    if (vg == 0)
#pragma unroll
        for (int r = 0; r < 4; r++) z[(size_t)blk * 64 + dg * 4 + r] = zacc[r];
}

// ---------------------------------------------------------------------------
// Pass 2: per (b,h), turn per-chunk S,z into exclusive prefix (causal)
// or total-sum broadcast (non-causal). grid = 32, block = 256.
// ---------------------------------------------------------------------------
__global__ void __launch_bounds__(256) prefix_k(float* __restrict__ S,
                                                float* __restrict__ z,
                                                const int* __restrict__ causal) {
    const int bh = blockIdx.x;
    const int caus = *causal;
    for (int e = threadIdx.x; e < 4096; e += 256) {
        float run = 0.f;
        if (caus) {
            for (int c = 0; c < NCK; c++) {
                size_t idx = ((size_t)bh * NCK + c) * 4096 + e;
                float t = S[idx]; S[idx] = run; run += t;
            }
        } else {
            for (int c = 0; c < NCK; c++) run += S[((size_t)bh * NCK + c) * 4096 + e];
            for (int c = 0; c < NCK; c++) S[((size_t)bh * NCK + c) * 4096 + e] = run;
        }
    }
    if (threadIdx.x < 64) {
        int e = threadIdx.x;
        float run = 0.f;
        if (caus) {
            for (int c = 0; c < NCK; c++) {
                size_t idx = ((size_t)bh * NCK + c) * 64 + e;
                float t = z[idx]; z[idx] = run; run += t;
            }
        } else {
            for (int c = 0; c < NCK; c++) run += z[((size_t)bh * NCK + c) * 64 + e];
            for (int c = 0; c < NCK; c++) z[((size_t)bh * NCK + c) * 64 + e] = run;
        }
    }
}

// ---------------------------------------------------------------------------
// Pass 3: per-chunk output.
//   A = tril(q k^T) (128x128), out = (q·S + A·v) / (q·z + rowsum(A) + eps)
// grid = 512, block = 256; dyn smem ~177 KB.  Writes (B,N,E) layout.
// ---------------------------------------------------------------------------
__global__ void __launch_bounds__(256) chunk_out(const float* __restrict__ q,
                                                 const float* __restrict__ k,
                                                 const float* __restrict__ v,
                                                 const float* __restrict__ S,
                                                 const float* __restrict__ z,
                                                 const int* __restrict__ causal,
                                                 float* __restrict__ out) {
    extern __shared__ float sm[];
    float* qs = sm;              // 128*64          = 8192
    float* kT = qs + 8192;       // 64*132 (padded) = 8448
    float* vs = kT + 8448;       // 128*64          = 8192
    float* Ss = vs + 8192;       // 64*64           = 4096
    float* zs = Ss + 4096;       // 64
    float* As = zs + 64;         // 128*128         = 16384

    const int blk = blockIdx.x;
    const int c = blk & 15, bh = blk >> 4;
    const int b = bh >> 4, h = bh & 15;
    const int tid = threadIdx.x;
    const int caus = *causal;

    const size_t base = ((size_t)bh * NSEQ + (size_t)c * CHK) * DD;
    const float4* q4 = (const float4*)(q + base);
    const float4* k4 = (const float4*)(k + base);
    const float4* v4 = (const float4*)(v + base);
    for (int idx = tid; idx < 2048; idx += 256) {
        ((float4*)qs)[idx] = q4[idx];
        ((float4*)vs)[idx] = v4[idx];
        float4 kk = k4[idx];
        int i = idx >> 4, d4 = (idx & 15) << 2;
        kT[(d4 + 0) * 132 + i] = kk.x;
        kT[(d4 + 1) * 132 + i] = kk.y;
        kT[(d4 + 2) * 132 + i] = kk.z;
        kT[(d4 + 3) * 132 + i] = kk.w;
    }
    const float4* S4 = (const float4*)(S + (size_t)blk * 4096);
    for (int i = tid; i < 1024; i += 256) ((float4*)Ss)[i] = S4[i];
    if (tid < 64) zs[tid] = z[(size_t)blk * 64 + tid];
    __syncthreads();

    const int rg = tid >> 4, cgl = tid & 15;

    if (caus) {
        // A tile: rows rg*8..+7, cols cgl*8..+7
        float accA[8][8] = {};
        for (int d = 0; d < 64; d++) {
            float qv[8];
#pragma unroll
            for (int i = 0; i < 8; i++) qv[i] = qs[(rg * 8 + i) * 64 + d];
            float4 k0 = *(const float4*)&kT[d * 132 + cgl * 8];
            float4 k1 = *(const float4*)&kT[d * 132 + cgl * 8 + 4];
            float kv[8] = {k0.x, k0.y, k0.z, k0.w, k1.x, k1.y, k1.z, k1.w};
#pragma unroll
            for (int i = 0; i < 8; i++)
#pragma unroll
                for (int j = 0; j < 8; j++) accA[i][j] += qv[i] * kv[j];
        }
#pragma unroll
        for (int i = 0; i < 8; i++) {
            int row = rg * 8 + i;
#pragma unroll
            for (int j = 0; j < 8; j++) {
                int col = cgl * 8 + j;
                As[row * 128 + col] = (col <= row) ? accA[i][j] : 0.f;
            }
        }
        __syncthreads();
    }

    // Output: rows rg*8..+7, value-cols cgl*4..+3
    float acc[8][4] = {};
    float den[8] = {};
    for (int d = 0; d < 64; d++) {
        float zv = zs[d];
        float4 sv = *(const float4*)&Ss[d * 64 + cgl * 4];
#pragma unroll
        for (int i = 0; i < 8; i++) {
            float qv = qs[(rg * 8 + i) * 64 + d];
            den[i] += qv * zv;
            acc[i][0] += qv * sv.x;
            acc[i][1] += qv * sv.y;
            acc[i][2] += qv * sv.z;
            acc[i][3] += qv * sv.w;
        }
    }
    if (caus) {
        for (int j = 0; j < 128; j++) {
            float4 vv = *(const float4*)&vs[j * 64 + cgl * 4];
#pragma unroll
            for (int i = 0; i < 8; i++) {
                float a = As[(rg * 8 + i) * 128 + j];
                den[i] += a;
                acc[i][0] += a * vv.x;
                acc[i][1] += a * vv.y;
                acc[i][2] += a * vv.z;
                acc[i][3] += a * vv.w;
            }
        }
    }
#pragma unroll
    for (int i = 0; i < 8; i++) {
        int rowg = c * CHK + rg * 8 + i;
        float inv = 1.f / (den[i] + EPSV);
        float4 o;
        o.x = acc[i][0] * inv; o.y = acc[i][1] * inv;
        o.z = acc[i][2] * inv; o.w = acc[i][3] * inv;
        size_t oidx = ((size_t)b * NSEQ + rowg) * EE + h * 64 + cgl * 4;
        *(float4*)&out[oidx] = o;
    }
}

// ---------------------------------------------------------------------------
extern "C" void kernel_launch(void* const* d_in, const int* in_sizes, int n_in,
                              void* d_out, int out_size) {
    const float* Q  = (const float*)d_in[0];
    const float* K  = (const float*)d_in[1];
    const float* V  = (const float*)d_in[2];
    const float* Wq = (const float*)d_in[3];
    const float* Wk = (const float*)d_in[4];
    const float* Wv = (const float*)d_in[5];
    const float* Wo = (const float*)d_in[6];
    const int* causal = (const int*)d_in[7];
    float* out = (float*)d_out;

    float *qb, *kb, *vb, *ab, *Sb, *zb;
    cudaGetSymbolAddress((void**)&qb, g_q);
    cudaGetSymbolAddress((void**)&kb, g_k);
    cudaGetSymbolAddress((void**)&vb, g_v);
    cudaGetSymbolAddress((void**)&ab, g_attn);
    cudaGetSymbolAddress((void**)&Sb, g_S);
    cudaGetSymbolAddress((void**)&zb, g_z);

    cudaFuncSetAttribute(chunk_kv, cudaFuncAttributeMaxDynamicSharedMemorySize, 65536);
    cudaFuncSetAttribute(chunk_out, cudaFuncAttributeMaxDynamicSharedMemorySize, 181504);

    dim3 grid(8, 32);  // (N/128, M/128)
    gemm_nt<true,  true ><<<grid, 256>>>(Q, Wq, qb);
    gemm_nt<true,  true ><<<grid, 256>>>(K, Wk, kb);
    gemm_nt<false, true ><<<grid, 256>>>(V, Wv, vb);

    chunk_kv<<<BB * HH * NCK, 256, 65536>>>(kb, vb, Sb, zb);
    prefix_k<<<BB * HH, 256>>>(Sb, zb, causal);
    chunk_out<<<BB * HH * NCK, 256, 181504>>>(qb, kb, vb, Sb, zb, causal, ab);

    gemm_nt<false, false><<<grid, 256>>>(ab, Wo, out);
}

// round 2
// speedup vs baseline: 2.1415x; 2.1415x over previous
#include <cuda_runtime.h>
#include <math.h>

// Problem constants (fixed by setup_inputs)
#define BB    2
#define HH    16
#define NSEQ  2048
#define EE    1024
#define DD    64
#define CHK   128
#define NCK   16            // NSEQ / CHK
#define EPSV  1e-6f

// ---------------- scratch (device globals; no allocation allowed) ----------
__device__ float g_q[BB*HH*NSEQ*DD];     // 16 MB, (B,H,N,D)
__device__ float g_k[BB*HH*NSEQ*DD];
__device__ float g_v[BB*HH*NSEQ*DD];
__device__ float g_attn[BB*NSEQ*EE];     // attention out in (B,N,E)
__device__ float g_S[BB*HH*NCK*DD*DD];   // per-chunk K^T V (prefixed in-place)
__device__ float g_z[BB*HH*NCK*DD];      // per-chunk K colsum (prefixed)

// ---------------------------------------------------------------------------
__device__ __forceinline__ unsigned f2tf(float f) {
    unsigned u;
    asm("cvt.rna.tf32.f32 %0, %1;" : "=r"(u) : "f"(f));
    return u;
}

__device__ __forceinline__ void mma_tf32(float c[4], const unsigned a[4], const unsigned b[2]) {
    asm volatile(
        "mma.sync.aligned.m16n8k8.row.col.f32.tf32.tf32.f32 "
        "{%0,%1,%2,%3}, {%4,%5,%6,%7}, {%8,%9}, {%0,%1,%2,%3};\n"
        : "+f"(c[0]), "+f"(c[1]), "+f"(c[2]), "+f"(c[3])
        : "r"(a[0]), "r"(a[1]), "r"(a[2]), "r"(a[3]), "r"(b[0]), "r"(b[1]));
}

// ---------------------------------------------------------------------------
// Tensor-core NT GEMM (TF32): C[m,n] = sum_k A[m,k] * W[n,k]
// M=4096, N=1024, K=1024.  FMAP: elu+1 epilogue.  BHND: scatter to (B,H,N,D).
// 128x128 CTA tile, BK=32, 8 warps (4x2), 32x64 warp tile.
// smem layout [k][m] stride 136 with XOR swizzle on row index; conflict-free
// for both STS and all fragment LDS.
// ---------------------------------------------------------------------------
template<bool FMAP, bool BHND>
__global__ void __launch_bounds__(256, 2) gemm_tc(const float* __restrict__ A,
                                                  const float* __restrict__ W,
                                                  float* __restrict__ C) {
    __shared__ unsigned As[32 * 136];
    __shared__ unsigned Bs[32 * 136];
    const int tid  = threadIdx.x;
    const int lane = tid & 31, warp = tid >> 5;
    const int bm = blockIdx.y * 128, bn = blockIdx.x * 128;
    const int wm = (warp >> 1) * 32, wn = (warp & 1) * 64;
    const int g = lane >> 2, tg = lane & 3;

    float acc[2][8][4];
#pragma unroll
    for (int mi = 0; mi < 2; mi++)
#pragma unroll
        for (int nj = 0; nj < 8; nj++)
#pragma unroll
            for (int x = 0; x < 4; x++) acc[mi][nj][x] = 0.f;

    for (int k0 = 0; k0 < 1024; k0 += 32) {
#pragma unroll
        for (int it = 0; it < 4; it++) {
            int i  = tid + it * 256;          // [0,1024)
            int r  = i >> 3;                  // row 0..127
            int c4 = (i & 7) << 2;            // k offset 0..28
            int swz = ((c4 >> 2) & 7) << 2;   // same for the 4 stored k's
            float4 va = *(const float4*)(A + (size_t)(bm + r) * 1024 + k0 + c4);
            float4 vb = *(const float4*)(W + (size_t)(bn + r) * 1024 + k0 + c4);
            int rr = r ^ swz;
            As[(c4 + 0) * 136 + rr] = f2tf(va.x);
            As[(c4 + 1) * 136 + rr] = f2tf(va.y);
            As[(c4 + 2) * 136 + rr] = f2tf(va.z);
            As[(c4 + 3) * 136 + rr] = f2tf(va.w);
            Bs[(c4 + 0) * 136 + rr] = f2tf(vb.x);
            Bs[(c4 + 1) * 136 + rr] = f2tf(vb.y);
            Bs[(c4 + 2) * 136 + rr] = f2tf(vb.z);
            Bs[(c4 + 3) * 136 + rr] = f2tf(vb.w);
        }
        __syncthreads();

#pragma unroll
        for (int ks = 0; ks < 4; ks++) {
            const int kb = ks * 8;
            const int krow0 = (kb + tg) * 136;
            const int krow1 = (kb + tg + 4) * 136;
            const int swz0 = ((2 * ks) & 7) << 2;
            const int swz1 = ((2 * ks + 1) & 7) << 2;

            unsigned a[2][4], b[8][2];
#pragma unroll
            for (int mi = 0; mi < 2; mi++) {
                int m = wm + mi * 16 + g;
                a[mi][0] = As[krow0 + ((m)     ^ swz0)];
                a[mi][1] = As[krow0 + ((m + 8) ^ swz0)];
                a[mi][2] = As[krow1 + ((m)     ^ swz1)];
                a[mi][3] = As[krow1 + ((m + 8) ^ swz1)];
            }
#pragma unroll
            for (int nj = 0; nj < 8; nj++) {
                int n = wn + nj * 8 + g;
                b[nj][0] = Bs[krow0 + (n ^ swz0)];
                b[nj][1] = Bs[krow1 + (n ^ swz1)];
            }
#pragma unroll
            for (int mi = 0; mi < 2; mi++)
#pragma unroll
                for (int nj = 0; nj < 8; nj++)
                    mma_tf32(acc[mi][nj], a[mi], b[nj]);
        }
        __syncthreads();
    }

    // epilogue
#pragma unroll
    for (int mi = 0; mi < 2; mi++) {
#pragma unroll
        for (int nj = 0; nj < 8; nj++) {
            int row0 = bm + wm + mi * 16 + g;
            int col0 = bn + wn + nj * 8 + 2 * tg;
#pragma unroll
            for (int half = 0; half < 2; half++) {
                int row = row0 + half * 8;
                float v0 = acc[mi][nj][half * 2 + 0];
                float v1 = acc[mi][nj][half * 2 + 1];
                if (FMAP) {
                    v0 = (v0 > 0.f) ? (v0 + 1.f) : expf(v0);
                    v1 = (v1 > 0.f) ? (v1 + 1.f) : expf(v1);
                }
                size_t idx;
                if (BHND) {
                    int bb = row >> 11, n = row & 2047;
                    int h = col0 >> 6, d = col0 & 63;
                    idx = ((((size_t)bb * HH + h) * NSEQ + n) * DD + d);
                } else {
                    idx = (size_t)row * 1024 + col0;
                }
                *(float2*)&C[idx] = make_float2(v0, v1);
            }
        }
    }
}

// ---------------------------------------------------------------------------
// Pass 1: per-chunk S_c[d][v] = sum_i k[i,d]*v[i,v], z_c[d] = sum_i k[i,d]
// grid = BB*HH*NCK = 512, block = 256; dyn smem = 64 KB
// ---------------------------------------------------------------------------
__global__ void __launch_bounds__(256) chunk_kv(const float* __restrict__ k,
                                                const float* __restrict__ v,
                                                float* __restrict__ S,
                                                float* __restrict__ z) {
    extern __shared__ float sm[];
    float* ks = sm;          // 128*64
    float* vs = sm + 8192;   // 128*64
    const int blk = blockIdx.x;
    const int c = blk & 15, bh = blk >> 4;
    const size_t base = ((size_t)bh * NSEQ + (size_t)c * CHK) * DD;
    const float4* k4 = (const float4*)(k + base);
    const float4* v4 = (const float4*)(v + base);
    for (int i = threadIdx.x; i < 2048; i += 256) {
        ((float4*)ks)[i] = k4[i];
        ((float4*)vs)[i] = v4[i];
    }
    __syncthreads();

    const int dg = threadIdx.x >> 4, vg = threadIdx.x & 15;
    float acc[4][4] = {};
    float zacc[4]  = {};
    for (int i = 0; i < 128; i++) {
        float4 kv = *(const float4*)&ks[i * 64 + dg * 4];
        float4 vv = *(const float4*)&vs[i * 64 + vg * 4];
        float kr[4] = {kv.x, kv.y, kv.z, kv.w};
        float vc[4] = {vv.x, vv.y, vv.z, vv.w};
#pragma unroll
        for (int r = 0; r < 4; r++) {
            zacc[r] += kr[r];
#pragma unroll
            for (int cc = 0; cc < 4; cc++) acc[r][cc] += kr[r] * vc[cc];
        }
    }
    const size_t sb = (size_t)blk * 4096;
#pragma unroll
    for (int r = 0; r < 4; r++)
#pragma unroll
        for (int cc = 0; cc < 4; cc++)
            S[sb + (size_t)(dg * 4 + r) * 64 + vg * 4 + cc] = acc[r][cc];
    if (vg == 0)
#pragma unroll
        for (int r = 0; r < 4; r++) z[(size_t)blk * 64 + dg * 4 + r] = zacc[r];
}

// ---------------------------------------------------------------------------
// Pass 2: per (b,h), turn per-chunk S,z into exclusive prefix (causal)
// or total-sum broadcast (non-causal). grid = 32, block = 256.
// ---------------------------------------------------------------------------
__global__ void __launch_bounds__(256) prefix_k(float* __restrict__ S,
                                                float* __restrict__ z,
                                                const int* __restrict__ causal) {
    const int bh = blockIdx.x;
    const int caus = *causal;
    for (int e = threadIdx.x; e < 4096; e += 256) {
        float run = 0.f;
        if (caus) {
            for (int c = 0; c < NCK; c++) {
                size_t idx = ((size_t)bh * NCK + c) * 4096 + e;
                float t = S[idx]; S[idx] = run; run += t;
            }
        } else {
            for (int c = 0; c < NCK; c++) run += S[((size_t)bh * NCK + c) * 4096 + e];
            for (int c = 0; c < NCK; c++) S[((size_t)bh * NCK + c) * 4096 + e] = run;
        }
    }
    if (threadIdx.x < 64) {
        int e = threadIdx.x;
        float run = 0.f;
        if (caus) {
            for (int c = 0; c < NCK; c++) {
                size_t idx = ((size_t)bh * NCK + c) * 64 + e;
                float t = z[idx]; z[idx] = run; run += t;
            }
        } else {
            for (int c = 0; c < NCK; c++) run += z[((size_t)bh * NCK + c) * 64 + e];
            for (int c = 0; c < NCK; c++) z[((size_t)bh * NCK + c) * 64 + e] = run;
        }
    }
}

// ---------------------------------------------------------------------------
// Pass 3: per-chunk output.
//   A = tril(q k^T) (128x128), out = (q·S + A·v) / (q·z + rowsum(A) + eps)
// grid = 512, block = 256; dyn smem ~177 KB.  Writes (B,N,E) layout.
// ---------------------------------------------------------------------------
__global__ void __launch_bounds__(256) chunk_out(const float* __restrict__ q,
                                                 const float* __restrict__ k,
                                                 const float* __restrict__ v,
                                                 const float* __restrict__ S,
                                                 const float* __restrict__ z,
                                                 const int* __restrict__ causal,
                                                 float* __restrict__ out) {
    extern __shared__ float sm[];
    float* qs = sm;              // 128*64          = 8192
    float* kT = qs + 8192;       // 64*132 (padded) = 8448
    float* vs = kT + 8448;       // 128*64          = 8192
    float* Ss = vs + 8192;       // 64*64           = 4096
    float* zs = Ss + 4096;       // 64
    float* As = zs + 64;         // 128*128         = 16384

    const int blk = blockIdx.x;
    const int c = blk & 15, bh = blk >> 4;
    const int b = bh >> 4, h = bh & 15;
    const int tid = threadIdx.x;
    const int caus = *causal;

    const size_t base = ((size_t)bh * NSEQ + (size_t)c * CHK) * DD;
    const float4* q4 = (const float4*)(q + base);
    const float4* k4 = (const float4*)(k + base);
    const float4* v4 = (const float4*)(v + base);
    for (int idx = tid; idx < 2048; idx += 256) {
        ((float4*)qs)[idx] = q4[idx];
        ((float4*)vs)[idx] = v4[idx];
        float4 kk = k4[idx];
        int i = idx >> 4, d4 = (idx & 15) << 2;
        kT[(d4 + 0) * 132 + i] = kk.x;
        kT[(d4 + 1) * 132 + i] = kk.y;
        kT[(d4 + 2) * 132 + i] = kk.z;
        kT[(d4 + 3) * 132 + i] = kk.w;
    }
    const float4* S4 = (const float4*)(S + (size_t)blk * 4096);
    for (int i = tid; i < 1024; i += 256) ((float4*)Ss)[i] = S4[i];
    if (tid < 64) zs[tid] = z[(size_t)blk * 64 + tid];
    __syncthreads();

    const int rg = tid >> 4, cgl = tid & 15;

    if (caus) {
        float accA[8][8] = {};
        for (int d = 0; d < 64; d++) {
            float qv[8];
#pragma unroll
            for (int i = 0; i < 8; i++) qv[i] = qs[(rg * 8 + i) * 64 + d];
            float4 k0 = *(const float4*)&kT[d * 132 + cgl * 8];
            float4 k1 = *(const float4*)&kT[d * 132 + cgl * 8 + 4];
            float kv[8] = {k0.x, k0.y, k0.z, k0.w, k1.x, k1.y, k1.z, k1.w};
#pragma unroll
            for (int i = 0; i < 8; i++)
#pragma unroll
                for (int j = 0; j < 8; j++) accA[i][j] += qv[i] * kv[j];
        }
#pragma unroll
        for (int i = 0; i < 8; i++) {
            int row = rg * 8 + i;
#pragma unroll
            for (int j = 0; j < 8; j++) {
                int col = cgl * 8 + j;
                As[row * 128 + col] = (col <= row) ? accA[i][j] : 0.f;
            }
        }
        __syncthreads();
    }

    float acc[8][4] = {};
    float den[8] = {};
    for (int d = 0; d < 64; d++) {
        float zv = zs[d];
        float4 sv = *(const float4*)&Ss[d * 64 + cgl * 4];
#pragma unroll
        for (int i = 0; i < 8; i++) {
            float qv = qs[(rg * 8 + i) * 64 + d];
            den[i] += qv * zv;
            acc[i][0] += qv * sv.x;
            acc[i][1] += qv * sv.y;
            acc[i][2] += qv * sv.z;
            acc[i][3] += qv * sv.w;
        }
    }
    if (caus) {
        for (int j = 0; j < 128; j++) {
            float4 vv = *(const float4*)&vs[j * 64 + cgl * 4];
#pragma unroll
            for (int i = 0; i < 8; i++) {
                float a = As[(rg * 8 + i) * 128 + j];
                den[i] += a;
                acc[i][0] += a * vv.x;
                acc[i][1] += a * vv.y;
                acc[i][2] += a * vv.z;
                acc[i][3] += a * vv.w;
            }
        }
    }
#pragma unroll
    for (int i = 0; i < 8; i++) {
        int rowg = c * CHK + rg * 8 + i;
        float inv = 1.f / (den[i] + EPSV);
        float4 o;
        o.x = acc[i][0] * inv; o.y = acc[i][1] * inv;
        o.z = acc[i][2] * inv; o.w = acc[i][3] * inv;
        size_t oidx = ((size_t)b * NSEQ + rowg) * EE + h * 64 + cgl * 4;
        *(float4*)&out[oidx] = o;
    }
}

// ---------------------------------------------------------------------------
extern "C" void kernel_launch(void* const* d_in, const int* in_sizes, int n_in,
                              void* d_out, int out_size) {
    const float* Q  = (const float*)d_in[0];
    const float* K  = (const float*)d_in[1];
    const float* V  = (const float*)d_in[2];
    const float* Wq = (const float*)d_in[3];
    const float* Wk = (const float*)d_in[4];
    const float* Wv = (const float*)d_in[5];
    const float* Wo = (const float*)d_in[6];
    const int* causal = (const int*)d_in[7];
    float* out = (float*)d_out;

    float *qb, *kb, *vb, *ab, *Sb, *zb;
    cudaGetSymbolAddress((void**)&qb, g_q);
    cudaGetSymbolAddress((void**)&kb, g_k);
    cudaGetSymbolAddress((void**)&vb, g_v);
    cudaGetSymbolAddress((void**)&ab, g_attn);
    cudaGetSymbolAddress((void**)&Sb, g_S);
    cudaGetSymbolAddress((void**)&zb, g_z);

    cudaFuncSetAttribute(chunk_kv, cudaFuncAttributeMaxDynamicSharedMemorySize, 65536);
    cudaFuncSetAttribute(chunk_out, cudaFuncAttributeMaxDynamicSharedMemorySize, 181504);

    dim3 grid(8, 32);  // (N/128, M/128)
    gemm_tc<true,  true ><<<grid, 256>>>(Q, Wq, qb);
    gemm_tc<true,  true ><<<grid, 256>>>(K, Wk, kb);
    gemm_tc<false, true ><<<grid, 256>>>(V, Wv, vb);

    chunk_kv<<<BB * HH * NCK, 256, 65536>>>(kb, vb, Sb, zb);
    prefix_k<<<BB * HH, 256>>>(Sb, zb, causal);
    chunk_out<<<BB * HH * NCK, 256, 181504>>>(qb, kb, vb, Sb, zb, causal, ab);

    gemm_tc<false, false><<<grid, 256>>>(ab, Wo, out);
}

// round 3
// speedup vs baseline: 2.5619x; 1.1963x over previous
#include <cuda_runtime.h>
#include <math.h>

// Problem constants (fixed by setup_inputs)
#define BB    2
#define HH    16
#define NSEQ  2048
#define EE    1024
#define DD    64
#define CHK   128
#define NCK   16
#define EPSV  1e-6f

// GEMM tiling
#define BK    32
#define STRD  36                 // smem row stride (words); 36 mod 32 = 4 -> conflict-free
#define OPW   (128 * STRD)       // words per operand per stage (4608)
#define STGW  (2 * OPW)          // words per stage (9216)
#define NSTG  3
#define GSMEM (NSTG * STGW * 4)  // 110592 bytes

// ---------------- scratch (device globals; no allocation allowed) ----------
__device__ float g_q[BB*HH*NSEQ*DD];
__device__ float g_k[BB*HH*NSEQ*DD];
__device__ float g_v[BB*HH*NSEQ*DD];
__device__ float g_attn[BB*NSEQ*EE];
__device__ float g_S[BB*HH*NCK*DD*DD];
__device__ float g_z[BB*HH*NCK*DD];

// ---------------------------------------------------------------------------
__device__ __forceinline__ unsigned f2tf(float f) {
    unsigned u;
    asm("cvt.rna.tf32.f32 %0, %1;" : "=r"(u) : "f"(f));
    return u;
}

__device__ __forceinline__ void mma_tf32(float c[4], const unsigned a[4], const unsigned b[2]) {
    asm volatile(
        "mma.sync.aligned.m16n8k8.row.col.f32.tf32.tf32.f32 "
        "{%0,%1,%2,%3}, {%4,%5,%6,%7}, {%8,%9}, {%0,%1,%2,%3};\n"
        : "+f"(c[0]), "+f"(c[1]), "+f"(c[2]), "+f"(c[3])
        : "r"(a[0]), "r"(a[1]), "r"(a[2]), "r"(a[3]), "r"(b[0]), "r"(b[1]));
}

__device__ __forceinline__ void cp16(float* dst, const float* src) {
    unsigned d = (unsigned)__cvta_generic_to_shared(dst);
    asm volatile("cp.async.cg.shared.global [%0], [%1], 16;\n" :: "r"(d), "l"(src));
}

// ---------------------------------------------------------------------------
// Pipelined TF32 NT-GEMM body: C[m,n] = sum_k A[m,k]*W[n,k]; M rows by grid.y,
// N=1024 cols by grid.x, K=1024. smem [m][k] stride 36, 3-stage cp.async.
// ---------------------------------------------------------------------------
__device__ __forceinline__ void gemm_body(const float* __restrict__ A,
                                          const float* __restrict__ W,
                                          float* __restrict__ C,
                                          bool fmap, bool bhnd, float* sm) {
    const int tid = threadIdx.x, lane = tid & 31, warp = tid >> 5;
    const int bm = blockIdx.y * 128, bn = blockIdx.x * 128;
    const int wm = (warp >> 1) * 32, wn = (warp & 1) * 64;
    const int g = lane >> 2, tg = lane & 3;

    float acc[2][8][4];
#pragma unroll
    for (int mi = 0; mi < 2; mi++)
#pragma unroll
        for (int nj = 0; nj < 8; nj++)
#pragma unroll
            for (int x = 0; x < 4; x++) acc[mi][nj][x] = 0.f;

    // per-thread load coords: 4 iters cover 128 rows x 8 segs (x4 floats)
    const int lr0 = tid >> 3;            // +32 per iter
    const int lc4 = (tid & 7) << 2;

    auto issue = [&](int buf, int k0) {
        float* dA = sm + buf * STGW;
        float* dB = dA + OPW;
#pragma unroll
        for (int it = 0; it < 4; it++) {
            int r = lr0 + it * 32;
            cp16(dA + r * STRD + lc4, A + (size_t)(bm + r) * 1024 + k0 + lc4);
            cp16(dB + r * STRD + lc4, W + (size_t)(bn + r) * 1024 + k0 + lc4);
        }
    };

    issue(0, 0);
    asm volatile("cp.async.commit_group;\n" ::: "memory");
    issue(1, BK);
    asm volatile("cp.async.commit_group;\n" ::: "memory");

    for (int t = 0; t < 32; t++) {
        asm volatile("cp.async.wait_group 1;\n" ::: "memory");
        __syncthreads();
        if (t + 2 < 32) issue((t + 2) % NSTG, (t + 2) * BK);
        asm volatile("cp.async.commit_group;\n" ::: "memory");

        const float* As = sm + (t % NSTG) * STGW;
        const float* Bs = As + OPW;
#pragma unroll
        for (int ks = 0; ks < 4; ks++) {
            const int kb = ks * 8;
            unsigned a[2][4], b[8][2];
#pragma unroll
            for (int mi = 0; mi < 2; mi++) {
                int m = wm + mi * 16 + g;
                a[mi][0] = f2tf(As[(m)      * STRD + kb + tg]);
                a[mi][1] = f2tf(As[(m + 8)  * STRD + kb + tg]);
                a[mi][2] = f2tf(As[(m)      * STRD + kb + tg + 4]);
                a[mi][3] = f2tf(As[(m + 8)  * STRD + kb + tg + 4]);
            }
#pragma unroll
            for (int nj = 0; nj < 8; nj++) {
                int n = wn + nj * 8 + g;
                b[nj][0] = f2tf(Bs[n * STRD + kb + tg]);
                b[nj][1] = f2tf(Bs[n * STRD + kb + tg + 4]);
            }
#pragma unroll
            for (int mi = 0; mi < 2; mi++)
#pragma unroll
                for (int nj = 0; nj < 8; nj++)
                    mma_tf32(acc[mi][nj], a[mi], b[nj]);
        }
    }

    // epilogue
#pragma unroll
    for (int mi = 0; mi < 2; mi++) {
#pragma unroll
        for (int nj = 0; nj < 8; nj++) {
            int row0 = bm + wm + mi * 16 + g;
            int col0 = bn + wn + nj * 8 + 2 * tg;
#pragma unroll
            for (int half = 0; half < 2; half++) {
                int row = row0 + half * 8;
                float v0 = acc[mi][nj][half * 2 + 0];
                float v1 = acc[mi][nj][half * 2 + 1];
                if (fmap) {
                    v0 = (v0 > 0.f) ? (v0 + 1.f) : expf(v0);
                    v1 = (v1 > 0.f) ? (v1 + 1.f) : expf(v1);
                }
                size_t idx;
                if (bhnd) {
                    int bb = row >> 11, n = row & 2047;
                    int h = col0 >> 6, d = col0 & 63;
                    idx = ((((size_t)bb * HH + h) * NSEQ + n) * DD + d);
                } else {
                    idx = (size_t)row * 1024 + col0;
                }
                *(float2*)&C[idx] = make_float2(v0, v1);
            }
        }
    }
}

// Fused Q/K/V projections: gridDim.z selects which one.
__global__ void __launch_bounds__(256, 2) gemm_qkv(const float* __restrict__ Q,
                                                   const float* __restrict__ K,
                                                   const float* __restrict__ V,
                                                   const float* __restrict__ Wq,
                                                   const float* __restrict__ Wk,
                                                   const float* __restrict__ Wv,
                                                   float* __restrict__ qb,
                                                   float* __restrict__ kb,
                                                   float* __restrict__ vb) {
    extern __shared__ float sm[];
    const int z = blockIdx.z;
    const float* A; const float* W; float* C; bool fmap;
    if (z == 0)      { A = Q; W = Wq; C = qb; fmap = true; }
    else if (z == 1) { A = K; W = Wk; C = kb; fmap = true; }
    else             { A = V; W = Wv; C = vb; fmap = false; }
    gemm_body(A, W, C, fmap, true, sm);
}

__global__ void __launch_bounds__(256, 2) gemm_out(const float* __restrict__ A,
                                                   const float* __restrict__ W,
                                                   float* __restrict__ C) {
    extern __shared__ float sm[];
    gemm_body(A, W, C, false, false, sm);
}

// ---------------------------------------------------------------------------
// Pass 1: per-chunk S_c[d][v] = sum_i k[i,d]*v[i,v], z_c[d] = sum_i k[i,d]
// ---------------------------------------------------------------------------
__global__ void __launch_bounds__(256) chunk_kv(const float* __restrict__ k,
                                                const float* __restrict__ v,
                                                float* __restrict__ S,
                                                float* __restrict__ z) {
    extern __shared__ float sm[];
    float* ks = sm;
    float* vs = sm + 8192;
    const int blk = blockIdx.x;
    const int c = blk & 15, bh = blk >> 4;
    const size_t base = ((size_t)bh * NSEQ + (size_t)c * CHK) * DD;
    const float4* k4 = (const float4*)(k + base);
    const float4* v4 = (const float4*)(v + base);
    for (int i = threadIdx.x; i < 2048; i += 256) {
        ((float4*)ks)[i] = k4[i];
        ((float4*)vs)[i] = v4[i];
    }
    __syncthreads();

    const int dg = threadIdx.x >> 4, vg = threadIdx.x & 15;
    float acc[4][4] = {};
    float zacc[4]  = {};
    for (int i = 0; i < 128; i++) {
        float4 kv = *(const float4*)&ks[i * 64 + dg * 4];
        float4 vv = *(const float4*)&vs[i * 64 + vg * 4];
        float kr[4] = {kv.x, kv.y, kv.z, kv.w};
        float vc[4] = {vv.x, vv.y, vv.z, vv.w};
#pragma unroll
        for (int r = 0; r < 4; r++) {
            zacc[r] += kr[r];
#pragma unroll
            for (int cc = 0; cc < 4; cc++) acc[r][cc] += kr[r] * vc[cc];
        }
    }
    const size_t sb = (size_t)blk * 4096;
#pragma unroll
    for (int r = 0; r < 4; r++)
#pragma unroll
        for (int cc = 0; cc < 4; cc++)
            S[sb + (size_t)(dg * 4 + r) * 64 + vg * 4 + cc] = acc[r][cc];
    if (vg == 0)
#pragma unroll
        for (int r = 0; r < 4; r++) z[(size_t)blk * 64 + dg * 4 + r] = zacc[r];
}

// ---------------------------------------------------------------------------
// Pass 2: exclusive prefix of per-chunk S,z (causal) / total broadcast.
// ---------------------------------------------------------------------------
__global__ void __launch_bounds__(256) prefix_k(float* __restrict__ S,
                                                float* __restrict__ z,
                                                const int* __restrict__ causal) {
    const int bh = blockIdx.x;
    const int caus = *causal;
    for (int e = threadIdx.x; e < 4096; e += 256) {
        float run = 0.f;
        if (caus) {
            for (int c = 0; c < NCK; c++) {
                size_t idx = ((size_t)bh * NCK + c) * 4096 + e;
                float t = S[idx]; S[idx] = run; run += t;
            }
        } else {
            for (int c = 0; c < NCK; c++) run += S[((size_t)bh * NCK + c) * 4096 + e];
            for (int c = 0; c < NCK; c++) S[((size_t)bh * NCK + c) * 4096 + e] = run;
        }
    }
    if (threadIdx.x < 64) {
        int e = threadIdx.x;
        float run = 0.f;
        if (caus) {
            for (int c = 0; c < NCK; c++) {
                size_t idx = ((size_t)bh * NCK + c) * 64 + e;
                float t = z[idx]; z[idx] = run; run += t;
            }
        } else {
            for (int c = 0; c < NCK; c++) run += z[((size_t)bh * NCK + c) * 64 + e];
            for (int c = 0; c < NCK; c++) z[((size_t)bh * NCK + c) * 64 + e] = run;
        }
    }
}

// ---------------------------------------------------------------------------
// Pass 3: per-chunk output.
// ---------------------------------------------------------------------------
__global__ void __launch_bounds__(256) chunk_out(const float* __restrict__ q,
                                                 const float* __restrict__ k,
                                                 const float* __restrict__ v,
                                                 const float* __restrict__ S,
                                                 const float* __restrict__ z,
                                                 const int* __restrict__ causal,
                                                 float* __restrict__ out) {
    extern __shared__ float sm[];
    float* qs = sm;              // 128*64
    float* kT = qs + 8192;       // 64*132
    float* vs = kT + 8448;       // 128*64
    float* Ss = vs + 8192;       // 64*64
    float* zs = Ss + 4096;       // 64
    float* As = zs + 64;         // 128*128

    const int blk = blockIdx.x;
    const int c = blk & 15, bh = blk >> 4;
    const int b = bh >> 4, h = bh & 15;
    const int tid = threadIdx.x;
    const int caus = *causal;

    const size_t base = ((size_t)bh * NSEQ + (size_t)c * CHK) * DD;
    const float4* q4 = (const float4*)(q + base);
    const float4* k4 = (const float4*)(k + base);
    const float4* v4 = (const float4*)(v + base);
    for (int idx = tid; idx < 2048; idx += 256) {
        ((float4*)qs)[idx] = q4[idx];
        ((float4*)vs)[idx] = v4[idx];
        float4 kk = k4[idx];
        int i = idx >> 4, d4 = (idx & 15) << 2;
        kT[(d4 + 0) * 132 + i] = kk.x;
        kT[(d4 + 1) * 132 + i] = kk.y;
        kT[(d4 + 2) * 132 + i] = kk.z;
        kT[(d4 + 3) * 132 + i] = kk.w;
    }
    const float4* S4 = (const float4*)(S + (size_t)blk * 4096);
    for (int i = tid; i < 1024; i += 256) ((float4*)Ss)[i] = S4[i];
    if (tid < 64) zs[tid] = z[(size_t)blk * 64 + tid];
    __syncthreads();

    const int rg = tid >> 4, cgl = tid & 15;

    if (caus) {
        float accA[8][8] = {};
        for (int d = 0; d < 64; d++) {
            float qv[8];
#pragma unroll
            for (int i = 0; i < 8; i++) qv[i] = qs[(rg * 8 + i) * 64 + d];
            float4 k0 = *(const float4*)&kT[d * 132 + cgl * 8];
            float4 k1 = *(const float4*)&kT[d * 132 + cgl * 8 + 4];
            float kv[8] = {k0.x, k0.y, k0.z, k0.w, k1.x, k1.y, k1.z, k1.w};
#pragma unroll
            for (int i = 0; i < 8; i++)
#pragma unroll
                for (int j = 0; j < 8; j++) accA[i][j] += qv[i] * kv[j];
        }
#pragma unroll
        for (int i = 0; i < 8; i++) {
            int row = rg * 8 + i;
#pragma unroll
            for (int j = 0; j < 8; j++) {
                int col = cgl * 8 + j;
                As[row * 128 + col] = (col <= row) ? accA[i][j] : 0.f;
            }
        }
        __syncthreads();
    }

    float acc[8][4] = {};
    float den[8] = {};
    for (int d = 0; d < 64; d++) {
        float zv = zs[d];
        float4 sv = *(const float4*)&Ss[d * 64 + cgl * 4];
#pragma unroll
        for (int i = 0; i < 8; i++) {
            float qv = qs[(rg * 8 + i) * 64 + d];
            den[i] += qv * zv;
            acc[i][0] += qv * sv.x;
            acc[i][1] += qv * sv.y;
            acc[i][2] += qv * sv.z;
            acc[i][3] += qv * sv.w;
        }
    }
    if (caus) {
        for (int j = 0; j < 128; j++) {
            float4 vv = *(const float4*)&vs[j * 64 + cgl * 4];
#pragma unroll
            for (int i = 0; i < 8; i++) {
                float a = As[(rg * 8 + i) * 128 + j];
                den[i] += a;
                acc[i][0] += a * vv.x;
                acc[i][1] += a * vv.y;
                acc[i][2] += a * vv.z;
                acc[i][3] += a * vv.w;
            }
        }
    }
#pragma unroll
    for (int i = 0; i < 8; i++) {
        int rowg = c * CHK + rg * 8 + i;
        float inv = 1.f / (den[i] + EPSV);
        float4 o;
        o.x = acc[i][0] * inv; o.y = acc[i][1] * inv;
        o.z = acc[i][2] * inv; o.w = acc[i][3] * inv;
        size_t oidx = ((size_t)b * NSEQ + rowg) * EE + h * 64 + cgl * 4;
        *(float4*)&out[oidx] = o;
    }
}

// ---------------------------------------------------------------------------
extern "C" void kernel_launch(void* const* d_in, const int* in_sizes, int n_in,
                              void* d_out, int out_size) {
    const float* Q  = (const float*)d_in[0];
    const float* K  = (const float*)d_in[1];
    const float* V  = (const float*)d_in[2];
    const float* Wq = (const float*)d_in[3];
    const float* Wk = (const float*)d_in[4];
    const float* Wv = (const float*)d_in[5];
    const float* Wo = (const float*)d_in[6];
    const int* causal = (const int*)d_in[7];
    float* out = (float*)d_out;

    float *qb, *kb, *vb, *ab, *Sb, *zb;
    cudaGetSymbolAddress((void**)&qb, g_q);
    cudaGetSymbolAddress((void**)&kb, g_k);
    cudaGetSymbolAddress((void**)&vb, g_v);
    cudaGetSymbolAddress((void**)&ab, g_attn);
    cudaGetSymbolAddress((void**)&Sb, g_S);
    cudaGetSymbolAddress((void**)&zb, g_z);

    cudaFuncSetAttribute(gemm_qkv, cudaFuncAttributeMaxDynamicSharedMemorySize, GSMEM);
    cudaFuncSetAttribute(gemm_out, cudaFuncAttributeMaxDynamicSharedMemorySize, GSMEM);
    cudaFuncSetAttribute(chunk_kv, cudaFuncAttributeMaxDynamicSharedMemorySize, 65536);
    cudaFuncSetAttribute(chunk_out, cudaFuncAttributeMaxDynamicSharedMemorySize, 181504);

    dim3 gq(8, 32, 3);
    gemm_qkv<<<gq, 256, GSMEM>>>(Q, K, V, Wq, Wk, Wv, qb, kb, vb);

    chunk_kv<<<BB * HH * NCK, 256, 65536>>>(kb, vb, Sb, zb);
    prefix_k<<<BB * HH, 256>>>(Sb, zb, causal);
    chunk_out<<<BB * HH * NCK, 256, 181504>>>(qb, kb, vb, Sb, zb, causal, ab);

    dim3 go(8, 32);
    gemm_out<<<go, 256, GSMEM>>>(ab, Wo, out);
}

// round 4
// speedup vs baseline: 3.0980x; 1.2093x over previous
#include <cuda_runtime.h>
#include <math.h>

// Problem constants (fixed by setup_inputs)
#define BB    2
#define HH    16
#define NSEQ  2048
#define EE    1024
#define DD    64
#define CHK   128
#define NCK   16
#define EPSV  1e-6f

// GEMM tiling
#define BK    32
#define STRD  36                 // smem row stride (words); mod 32 = 4 -> conflict-free
#define OPW   (128 * STRD)
#define STGW  (2 * OPW)
#define NSTG  3
#define GSMEM (NSTG * STGW * 4)  // 110592 bytes

// chunk_out_tc smem layout (floats)
#define CO_QS   0
#define CO_KS   (128 * 68)
#define CO_VT   (CO_KS + 128 * 68)
#define CO_STZ  (CO_VT + 64 * 132)
#define CO_AS   (CO_STZ + 72 * 68)
#define CO_TOT  (CO_AS + 128 * 132)          // 47648 floats
#define CO_SMEM (CO_TOT * 4)                 // 190592 bytes

// ---------------- scratch (device globals; no allocation allowed) ----------
__device__ float g_q[BB*HH*NSEQ*DD];
__device__ float g_k[BB*HH*NSEQ*DD];
__device__ float g_v[BB*HH*NSEQ*DD];
__device__ float g_attn[BB*NSEQ*EE];
__device__ float g_S[BB*HH*NCK*DD*DD];
__device__ float g_z[BB*HH*NCK*DD];
__device__ float g_rw[4 * EE * EE];          // tf32-rounded Wq,Wk,Wv,Wo

// ---------------------------------------------------------------------------
__device__ __forceinline__ unsigned f2tf(float f) {
    unsigned u;
    asm("cvt.rna.tf32.f32 %0, %1;" : "=r"(u) : "f"(f));
    return u;
}
__device__ __forceinline__ float tf32r(float f) { return __uint_as_float(f2tf(f)); }

__device__ __forceinline__ void mma_tf32(float c[4], const unsigned a[4], const unsigned b[2]) {
    asm volatile(
        "mma.sync.aligned.m16n8k8.row.col.f32.tf32.tf32.f32 "
        "{%0,%1,%2,%3}, {%4,%5,%6,%7}, {%8,%9}, {%0,%1,%2,%3};\n"
        : "+f"(c[0]), "+f"(c[1]), "+f"(c[2]), "+f"(c[3])
        : "r"(a[0]), "r"(a[1]), "r"(a[2]), "r"(a[3]), "r"(b[0]), "r"(b[1]));
}

__device__ __forceinline__ void cp16(float* dst, const float* src) {
    unsigned d = (unsigned)__cvta_generic_to_shared(dst);
    asm volatile("cp.async.cg.shared.global [%0], [%1], 16;\n" :: "r"(d), "l"(src));
}

// ---------------------------------------------------------------------------
// Prepass: round Wq,Wk,Wv,Wo to tf32-representable floats.
// grid (1024, 4), block 256: 1024*256 float4 = 1M floats per array.
// ---------------------------------------------------------------------------
__global__ void __launch_bounds__(256) round_w(const float* __restrict__ w0,
                                               const float* __restrict__ w1,
                                               const float* __restrict__ w2,
                                               const float* __restrict__ w3,
                                               float* __restrict__ dst) {
    const float* src = (blockIdx.y == 0) ? w0 : (blockIdx.y == 1) ? w1
                       : (blockIdx.y == 2) ? w2 : w3;
    float* d = dst + (size_t)blockIdx.y * (EE * EE);
    int i = blockIdx.x * 256 + threadIdx.x;
    float4 v = ((const float4*)src)[i];
    v.x = tf32r(v.x); v.y = tf32r(v.y); v.z = tf32r(v.z); v.w = tf32r(v.w);
    ((float4*)d)[i] = v;
}

// ---------------------------------------------------------------------------
// Pipelined TF32 NT-GEMM. W is pre-rounded (raw-bit B-fragments).
// ACVT: cvt A-fragments (true when A not pre-rounded).
// FMAP: elu+1 epilogue. BHND: scatter to (B,H,N,D) and round output to tf32.
// ---------------------------------------------------------------------------
template<bool ACVT, bool FMAP, bool BHND>
__device__ __forceinline__ void gemm_body(const float* __restrict__ A,
                                          const float* __restrict__ W,
                                          float* __restrict__ C, float* sm) {
    const int tid = threadIdx.x, lane = tid & 31, warp = tid >> 5;
    const int bm = blockIdx.y * 128, bn = blockIdx.x * 128;
    const int wm = (warp >> 1) * 32, wn = (warp & 1) * 64;
    const int g = lane >> 2, tg = lane & 3;

    float acc[2][8][4];
#pragma unroll
    for (int mi = 0; mi < 2; mi++)
#pragma unroll
        for (int nj = 0; nj < 8; nj++)
#pragma unroll
            for (int x = 0; x < 4; x++) acc[mi][nj][x] = 0.f;

    const int lr0 = tid >> 3;
    const int lc4 = (tid & 7) << 2;

    auto issue = [&](int buf, int k0) {
        float* dA = sm + buf * STGW;
        float* dB = dA + OPW;
#pragma unroll
        for (int it = 0; it < 4; it++) {
            int r = lr0 + it * 32;
            cp16(dA + r * STRD + lc4, A + (size_t)(bm + r) * 1024 + k0 + lc4);
            cp16(dB + r * STRD + lc4, W + (size_t)(bn + r) * 1024 + k0 + lc4);
        }
    };

    issue(0, 0);
    asm volatile("cp.async.commit_group;\n" ::: "memory");
    issue(1, BK);
    asm volatile("cp.async.commit_group;\n" ::: "memory");

    for (int t = 0; t < 32; t++) {
        asm volatile("cp.async.wait_group 1;\n" ::: "memory");
        __syncthreads();
        if (t + 2 < 32) issue((t + 2) % NSTG, (t + 2) * BK);
        asm volatile("cp.async.commit_group;\n" ::: "memory");

        const float* As = sm + (t % NSTG) * STGW;
        const float* Bs = As + OPW;
#pragma unroll
        for (int ks = 0; ks < 4; ks++) {
            const int kb = ks * 8;
            unsigned a[2][4], b[8][2];
#pragma unroll
            for (int mi = 0; mi < 2; mi++) {
                int m = wm + mi * 16 + g;
                if (ACVT) {
                    a[mi][0] = f2tf(As[(m)     * STRD + kb + tg]);
                    a[mi][1] = f2tf(As[(m + 8) * STRD + kb + tg]);
                    a[mi][2] = f2tf(As[(m)     * STRD + kb + tg + 4]);
                    a[mi][3] = f2tf(As[(m + 8) * STRD + kb + tg + 4]);
                } else {
                    a[mi][0] = __float_as_uint(As[(m)     * STRD + kb + tg]);
                    a[mi][1] = __float_as_uint(As[(m + 8) * STRD + kb + tg]);
                    a[mi][2] = __float_as_uint(As[(m)     * STRD + kb + tg + 4]);
                    a[mi][3] = __float_as_uint(As[(m + 8) * STRD + kb + tg + 4]);
                }
            }
#pragma unroll
            for (int nj = 0; nj < 8; nj++) {
                int n = wn + nj * 8 + g;
                b[nj][0] = __float_as_uint(Bs[n * STRD + kb + tg]);
                b[nj][1] = __float_as_uint(Bs[n * STRD + kb + tg + 4]);
            }
#pragma unroll
            for (int mi = 0; mi < 2; mi++)
#pragma unroll
                for (int nj = 0; nj < 8; nj++)
                    mma_tf32(acc[mi][nj], a[mi], b[nj]);
        }
    }

#pragma unroll
    for (int mi = 0; mi < 2; mi++) {
#pragma unroll
        for (int nj = 0; nj < 8; nj++) {
            int row0 = bm + wm + mi * 16 + g;
            int col0 = bn + wn + nj * 8 + 2 * tg;
#pragma unroll
            for (int half = 0; half < 2; half++) {
                int row = row0 + half * 8;
                float v0 = acc[mi][nj][half * 2 + 0];
                float v1 = acc[mi][nj][half * 2 + 1];
                if (FMAP) {
                    v0 = (v0 > 0.f) ? (v0 + 1.f) : expf(v0);
                    v1 = (v1 > 0.f) ? (v1 + 1.f) : expf(v1);
                }
                size_t idx;
                if (BHND) {
                    // round features so downstream mma can feed raw bits
                    v0 = tf32r(v0); v1 = tf32r(v1);
                    int bb = row >> 11, n = row & 2047;
                    int h = col0 >> 6, d = col0 & 63;
                    idx = ((((size_t)bb * HH + h) * NSEQ + n) * DD + d);
                } else {
                    idx = (size_t)row * 1024 + col0;
                }
                *(float2*)&C[idx] = make_float2(v0, v1);
            }
        }
    }
}

__global__ void __launch_bounds__(256, 2) gemm_qkv(const float* __restrict__ Q,
                                                   const float* __restrict__ K,
                                                   const float* __restrict__ V,
                                                   const float* __restrict__ RW,
                                                   float* __restrict__ qb,
                                                   float* __restrict__ kb,
                                                   float* __restrict__ vb) {
    extern __shared__ float sm[];
    const int z = blockIdx.z;
    const float* A; float* C;
    const float* W = RW + (size_t)z * (EE * EE);
    if (z == 0)      { A = Q; C = qb; }
    else if (z == 1) { A = K; C = kb; }
    else             { A = V; C = vb; }
    if (z < 2) gemm_body<true, true,  true>(A, W, C, sm);
    else       gemm_body<true, false, true>(A, W, C, sm);
}

__global__ void __launch_bounds__(256, 2) gemm_out(const float* __restrict__ A,
                                                   const float* __restrict__ RW,
                                                   float* __restrict__ C) {
    extern __shared__ float sm[];
    gemm_body<false, false, false>(A, RW + (size_t)3 * EE * EE, C, sm);
}

// ---------------------------------------------------------------------------
// Pass 1: per-chunk S_c[d][v] = sum_i k[i,d]*v[i,v], z_c[d] = sum_i k[i,d]
// ---------------------------------------------------------------------------
__global__ void __launch_bounds__(256) chunk_kv(const float* __restrict__ k,
                                                const float* __restrict__ v,
                                                float* __restrict__ S,
                                                float* __restrict__ z) {
    extern __shared__ float sm[];
    float* ks = sm;
    float* vs = sm + 8192;
    const int blk = blockIdx.x;
    const int c = blk & 15, bh = blk >> 4;
    const size_t base = ((size_t)bh * NSEQ + (size_t)c * CHK) * DD;
    const float4* k4 = (const float4*)(k + base);
    const float4* v4 = (const float4*)(v + base);
    for (int i = threadIdx.x; i < 2048; i += 256) {
        ((float4*)ks)[i] = k4[i];
        ((float4*)vs)[i] = v4[i];
    }
    __syncthreads();

    const int dg = threadIdx.x >> 4, vg = threadIdx.x & 15;
    float acc[4][4] = {};
    float zacc[4]  = {};
    for (int i = 0; i < 128; i++) {
        float4 kv = *(const float4*)&ks[i * 64 + dg * 4];
        float4 vv = *(const float4*)&vs[i * 64 + vg * 4];
        float kr[4] = {kv.x, kv.y, kv.z, kv.w};
        float vc[4] = {vv.x, vv.y, vv.z, vv.w};
#pragma unroll
        for (int r = 0; r < 4; r++) {
            zacc[r] += kr[r];
#pragma unroll
            for (int cc = 0; cc < 4; cc++) acc[r][cc] += kr[r] * vc[cc];
        }
    }
    const size_t sb = (size_t)blk * 4096;
#pragma unroll
    for (int r = 0; r < 4; r++)
#pragma unroll
        for (int cc = 0; cc < 4; cc++)
            S[sb + (size_t)(dg * 4 + r) * 64 + vg * 4 + cc] = acc[r][cc];
    if (vg == 0)
#pragma unroll
        for (int r = 0; r < 4; r++) z[(size_t)blk * 64 + dg * 4 + r] = zacc[r];
}

// ---------------------------------------------------------------------------
// Pass 2: exclusive prefix of per-chunk S,z (causal) / total broadcast.
// ---------------------------------------------------------------------------
__global__ void __launch_bounds__(256) prefix_k(float* __restrict__ S,
                                                float* __restrict__ z,
                                                const int* __restrict__ causal) {
    const int bh = blockIdx.x;
    const int caus = *causal;
    for (int e = threadIdx.x; e < 4096; e += 256) {
        float run = 0.f;
        if (caus) {
            for (int c = 0; c < NCK; c++) {
                size_t idx = ((size_t)bh * NCK + c) * 4096 + e;
                float t = S[idx]; S[idx] = run; run += t;
            }
        } else {
            for (int c = 0; c < NCK; c++) run += S[((size_t)bh * NCK + c) * 4096 + e];
            for (int c = 0; c < NCK; c++) S[((size_t)bh * NCK + c) * 4096 + e] = run;
        }
    }
    if (threadIdx.x < 64) {
        int e = threadIdx.x;
        float run = 0.f;
        if (caus) {
            for (int c = 0; c < NCK; c++) {
                size_t idx = ((size_t)bh * NCK + c) * 64 + e;
                float t = z[idx]; z[idx] = run; run += t;
            }
        } else {
            for (int c = 0; c < NCK; c++) run += z[((size_t)bh * NCK + c) * 64 + e];
            for (int c = 0; c < NCK; c++) z[((size_t)bh * NCK + c) * 64 + e] = run;
        }
    }
}

// ---------------------------------------------------------------------------
// Pass 3 (tensor cores): per-chunk output.
//   GEMM1: A = tril(q k^T)  (mma tf32), rowsum via butterfly
//   GEMM2: num = q·[S^T|z] + A·v  (z folded in as accumulator col 64)
//   out   = num / (den + eps), rounded to tf32 (feeds gemm_out raw).
// 8 warps, each owns 16 rows. All fragment LDS conflict-free.
// ---------------------------------------------------------------------------
__global__ void __launch_bounds__(256) chunk_out_tc(const float* __restrict__ q,
                                                    const float* __restrict__ k,
                                                    const float* __restrict__ v,
                                                    const float* __restrict__ S,
                                                    const float* __restrict__ z,
                                                    const int* __restrict__ causal,
                                                    float* __restrict__ out) {
    extern __shared__ float sm[];
    float* qs  = sm + CO_QS;     // [128][68]  q features (tf32-representable)
    float* ks  = sm + CO_KS;     // [128][68]  k features
    float* vT  = sm + CO_VT;     // [64][132]  v transposed [d_v][i]
    float* STz = sm + CO_STZ;    // [72][68]   rows 0-63: S^T, row 64: z, 65-71: 0
    float* As  = sm + CO_AS;     // [128][132] masked A

    const int blk = blockIdx.x;
    const int c = blk & 15, bh = blk >> 4;
    const int b = bh >> 4, h = bh & 15;
    const int tid = threadIdx.x;
    const int lane = tid & 31, warp = tid >> 5;
    const int g = lane >> 2, tg = lane & 3;
    const int caus = *causal;
    const int m0 = warp * 16;

    const size_t base = ((size_t)bh * NSEQ + (size_t)c * CHK) * DD;
    for (int idx = tid; idx < 2048; idx += 256) {
        int i = idx >> 4, d4 = (idx & 15) << 2;
        *(float4*)&qs[i * 68 + d4] = *(const float4*)(q + base + (size_t)idx * 4);
        *(float4*)&ks[i * 68 + d4] = *(const float4*)(k + base + (size_t)idx * 4);
        float4 vv = *(const float4*)(v + base + (size_t)idx * 4);
        vT[(d4 + 0) * 132 + i] = vv.x;
        vT[(d4 + 1) * 132 + i] = vv.y;
        vT[(d4 + 2) * 132 + i] = vv.z;
        vT[(d4 + 3) * 132 + i] = vv.w;
    }
    for (int idx = tid; idx < 1024; idx += 256) {
        int d = idx >> 4, j4 = (idx & 15) << 2;
        float4 ss = *(const float4*)(S + (size_t)blk * 4096 + (size_t)idx * 4);
        STz[(j4 + 0) * 68 + d] = ss.x;
        STz[(j4 + 1) * 68 + d] = ss.y;
        STz[(j4 + 2) * 68 + d] = ss.z;
        STz[(j4 + 3) * 68 + d] = ss.w;
    }
    if (tid < 64) STz[64 * 68 + tid] = z[(size_t)blk * 64 + tid];
    for (int idx = tid; idx < 7 * 68; idx += 256) STz[65 * 68 + idx] = 0.f;
    __syncthreads();

    const int r0 = m0 + g, r1 = r0 + 8;
    float den0 = 0.f, den1 = 0.f;

    if (caus) {
        float accA[16][4];
#pragma unroll
        for (int nj = 0; nj < 16; nj++)
#pragma unroll
            for (int x = 0; x < 4; x++) accA[nj][x] = 0.f;
#pragma unroll
        for (int kb = 0; kb < 64; kb += 8) {
            unsigned a[4];
            a[0] = __float_as_uint(qs[(r0) * 68 + kb + tg]);
            a[1] = __float_as_uint(qs[(r1) * 68 + kb + tg]);
            a[2] = __float_as_uint(qs[(r0) * 68 + kb + tg + 4]);
            a[3] = __float_as_uint(qs[(r1) * 68 + kb + tg + 4]);
#pragma unroll
            for (int nj = 0; nj < 16; nj++) {
                unsigned bf[2];
                bf[0] = __float_as_uint(ks[(nj * 8 + g) * 68 + kb + tg]);
                bf[1] = __float_as_uint(ks[(nj * 8 + g) * 68 + kb + tg + 4]);
                mma_tf32(accA[nj], a, bf);
            }
        }
#pragma unroll
        for (int nj = 0; nj < 16; nj++) {
            int c0 = nj * 8 + 2 * tg;
            float x00 = (c0     <= r0) ? accA[nj][0] : 0.f;
            float x01 = (c0 + 1 <= r0) ? accA[nj][1] : 0.f;
            float x10 = (c0     <= r1) ? accA[nj][2] : 0.f;
            float x11 = (c0 + 1 <= r1) ? accA[nj][3] : 0.f;
            den0 += x00 + x01;
            den1 += x10 + x11;
            *(float2*)&As[r0 * 132 + c0] = make_float2(x00, x01);
            *(float2*)&As[r1 * 132 + c0] = make_float2(x10, x11);
        }
        den0 += __shfl_xor_sync(0xffffffffu, den0, 1);
        den0 += __shfl_xor_sync(0xffffffffu, den0, 2);
        den1 += __shfl_xor_sync(0xffffffffu, den1, 1);
        den1 += __shfl_xor_sync(0xffffffffu, den1, 2);
        __syncthreads();
    }

    float acc[9][4];
#pragma unroll
    for (int nj = 0; nj < 9; nj++)
#pragma unroll
        for (int x = 0; x < 4; x++) acc[nj][x] = 0.f;

    // q · [S^T | z]  (k-dim = 64)
#pragma unroll
    for (int kb = 0; kb < 64; kb += 8) {
        unsigned a[4];
        a[0] = __float_as_uint(qs[(r0) * 68 + kb + tg]);
        a[1] = __float_as_uint(qs[(r1) * 68 + kb + tg]);
        a[2] = __float_as_uint(qs[(r0) * 68 + kb + tg + 4]);
        a[3] = __float_as_uint(qs[(r1) * 68 + kb + tg + 4]);
#pragma unroll
        for (int nj = 0; nj < 9; nj++) {
            unsigned bf[2];
            bf[0] = f2tf(STz[(nj * 8 + g) * 68 + kb + tg]);
            bf[1] = f2tf(STz[(nj * 8 + g) * 68 + kb + tg + 4]);
            mma_tf32(acc[nj], a, bf);
        }
    }
    // A · v  (k-dim = 128), causal only
    if (caus) {
#pragma unroll
        for (int kb = 0; kb < 128; kb += 8) {
            unsigned a[4];
            a[0] = f2tf(As[(r0) * 132 + kb + tg]);
            a[1] = f2tf(As[(r1) * 132 + kb + tg]);
            a[2] = f2tf(As[(r0) * 132 + kb + tg + 4]);
            a[3] = f2tf(As[(r1) * 132 + kb + tg + 4]);
#pragma unroll
            for (int nj = 0; nj < 8; nj++) {
                unsigned bf[2];
                bf[0] = __float_as_uint(vT[(nj * 8 + g) * 132 + kb + tg]);
                bf[1] = __float_as_uint(vT[(nj * 8 + g) * 132 + kb + tg + 4]);
                mma_tf32(acc[nj], a, bf);
            }
        }
    }

    // denominator: q·z sits in accumulator col 64 (tile 8, tg==0 lanes)
    float qz0 = __shfl_sync(0xffffffffu, acc[8][0], (lane & ~3));
    float qz1 = __shfl_sync(0xffffffffu, acc[8][2], (lane & ~3));
    float inv0 = 1.f / (den0 + qz0 + EPSV);
    float inv1 = 1.f / (den1 + qz1 + EPSV);

#pragma unroll
    for (int nj = 0; nj < 8; nj++) {
        int col = h * 64 + nj * 8 + 2 * tg;
        size_t o0 = ((size_t)b * NSEQ + (size_t)c * CHK + r0) * EE + col;
        size_t o1 = ((size_t)b * NSEQ + (size_t)c * CHK + r1) * EE + col;
        *(float2*)&out[o0] = make_float2(tf32r(acc[nj][0] * inv0), tf32r(acc[nj][1] * inv0));
        *(float2*)&out[o1] = make_float2(tf32r(acc[nj][2] * inv1), tf32r(acc[nj][3] * inv1));
    }
}

// ---------------------------------------------------------------------------
extern "C" void kernel_launch(void* const* d_in, const int* in_sizes, int n_in,
                              void* d_out, int out_size) {
    const float* Q  = (const float*)d_in[0];
    const float* K  = (const float*)d_in[1];
    const float* V  = (const float*)d_in[2];
    const float* Wq = (const float*)d_in[3];
    const float* Wk = (const float*)d_in[4];
    const float* Wv = (const float*)d_in[5];
    const float* Wo = (const float*)d_in[6];
    const int* causal = (const int*)d_in[7];
    float* out = (float*)d_out;

    float *qb, *kb, *vb, *ab, *Sb, *zb, *rw;
    cudaGetSymbolAddress((void**)&qb, g_q);
    cudaGetSymbolAddress((void**)&kb, g_k);
    cudaGetSymbolAddress((void**)&vb, g_v);
    cudaGetSymbolAddress((void**)&ab, g_attn);
    cudaGetSymbolAddress((void**)&Sb, g_S);
    cudaGetSymbolAddress((void**)&zb, g_z);
    cudaGetSymbolAddress((void**)&rw, g_rw);

    cudaFuncSetAttribute(gemm_qkv, cudaFuncAttributeMaxDynamicSharedMemorySize, GSMEM);
    cudaFuncSetAttribute(gemm_out, cudaFuncAttributeMaxDynamicSharedMemorySize, GSMEM);
    cudaFuncSetAttribute(chunk_kv, cudaFuncAttributeMaxDynamicSharedMemorySize, 65536);
    cudaFuncSetAttribute(chunk_out_tc, cudaFuncAttributeMaxDynamicSharedMemorySize, CO_SMEM);

    round_w<<<dim3(1024, 4), 256>>>(Wq, Wk, Wv, Wo, rw);

    dim3 gq(8, 32, 3);
    gemm_qkv<<<gq, 256, GSMEM>>>(Q, K, V, rw, qb, kb, vb);

    chunk_kv<<<BB * HH * NCK, 256, 65536>>>(kb, vb, Sb, zb);
    prefix_k<<<BB * HH, 256>>>(Sb, zb, causal);
    chunk_out_tc<<<BB * HH * NCK, 256, CO_SMEM>>>(qb, kb, vb, Sb, zb, causal, ab);

    dim3 go(8, 32);
    gemm_out<<<go, 256, GSMEM>>>(ab, rw, out);
}

// round 5
// speedup vs baseline: 3.2270x; 1.0416x over previous
#include <cuda_runtime.h>
#include <math.h>

// Problem constants (fixed by setup_inputs)
#define BB    2
#define HH    16
#define NSEQ  2048
#define EE    1024
#define DD    64
#define CHK   128
#define NCK   16
#define EPSV  1e-6f

// GEMM tiling
#define BK    32
#define STRD  36                 // smem row stride (words); mod 32 = 4 -> conflict-free
#define OPW   (128 * STRD)
#define STGW  (2 * OPW)
#define NSTG  3
#define GSMEM (NSTG * STGW * 4)  // 110592 bytes

// chunk_out_tc smem layout (floats)
#define CO_QS   0
#define CO_KS   (128 * 68)
#define CO_VT   (CO_KS + 128 * 68)
#define CO_STZ  (CO_VT + 64 * 132)
#define CO_AS   (CO_STZ + 72 * 68)
#define CO_TOT  (CO_AS + 128 * 132)
#define CO_SMEM (CO_TOT * 4)                 // 190592 bytes

// chunk_kv_tc smem (floats): kT [64][132] + vT [64][132]
#define KV_SMEM (2 * 64 * 132 * 4)           // 67584 bytes

// ---------------- scratch (device globals; no allocation allowed) ----------
__device__ float g_q[BB*HH*NSEQ*DD];
__device__ float g_k[BB*HH*NSEQ*DD];
__device__ float g_v[BB*HH*NSEQ*DD];
__device__ float g_attn[BB*NSEQ*EE];
__device__ float g_S[BB*HH*NCK*DD*DD];       // stored TRANSPOSED: [chunk][v][d]
__device__ float g_z[BB*HH*NCK*DD];
__device__ float g_rw[4 * EE * EE];          // tf32-rounded Wq,Wk,Wv,Wo

// ---------------------------------------------------------------------------
__device__ __forceinline__ unsigned f2tf(float f) {
    unsigned u;
    asm("cvt.rna.tf32.f32 %0, %1;" : "=r"(u) : "f"(f));
    return u;
}
__device__ __forceinline__ float tf32r(float f) { return __uint_as_float(f2tf(f)); }

__device__ __forceinline__ void mma_tf32(float c[4], const unsigned a[4], const unsigned b[2]) {
    asm volatile(
        "mma.sync.aligned.m16n8k8.row.col.f32.tf32.tf32.f32 "
        "{%0,%1,%2,%3}, {%4,%5,%6,%7}, {%8,%9}, {%0,%1,%2,%3};\n"
        : "+f"(c[0]), "+f"(c[1]), "+f"(c[2]), "+f"(c[3])
        : "r"(a[0]), "r"(a[1]), "r"(a[2]), "r"(a[3]), "r"(b[0]), "r"(b[1]));
}

__device__ __forceinline__ void cp16(float* dst, const float* src) {
    unsigned d = (unsigned)__cvta_generic_to_shared(dst);
    asm volatile("cp.async.cg.shared.global [%0], [%1], 16;\n" :: "r"(d), "l"(src));
}

// ---------------------------------------------------------------------------
// Prepass: round Wq,Wk,Wv,Wo to tf32-representable floats.
// ---------------------------------------------------------------------------
__global__ void __launch_bounds__(256) round_w(const float* __restrict__ w0,
                                               const float* __restrict__ w1,
                                               const float* __restrict__ w2,
                                               const float* __restrict__ w3,
                                               float* __restrict__ dst) {
    const float* src = (blockIdx.y == 0) ? w0 : (blockIdx.y == 1) ? w1
                       : (blockIdx.y == 2) ? w2 : w3;
    float* d = dst + (size_t)blockIdx.y * (EE * EE);
    int i = blockIdx.x * 256 + threadIdx.x;
    float4 v = ((const float4*)src)[i];
    v.x = tf32r(v.x); v.y = tf32r(v.y); v.z = tf32r(v.z); v.w = tf32r(v.w);
    ((float4*)d)[i] = v;
}

// ---------------------------------------------------------------------------
// Pipelined TF32 NT-GEMM. W is pre-rounded (raw-bit B-fragments).
// ---------------------------------------------------------------------------
template<bool ACVT, bool FMAP, bool BHND>
__device__ __forceinline__ void gemm_body(const float* __restrict__ A,
                                          const float* __restrict__ W,
                                          float* __restrict__ C, float* sm) {
    const int tid = threadIdx.x, lane = tid & 31, warp = tid >> 5;
    const int bm = blockIdx.y * 128, bn = blockIdx.x * 128;
    const int wm = (warp >> 1) * 32, wn = (warp & 1) * 64;
    const int g = lane >> 2, tg = lane & 3;

    float acc[2][8][4];
#pragma unroll
    for (int mi = 0; mi < 2; mi++)
#pragma unroll
        for (int nj = 0; nj < 8; nj++)
#pragma unroll
            for (int x = 0; x < 4; x++) acc[mi][nj][x] = 0.f;

    const int lr0 = tid >> 3;
    const int lc4 = (tid & 7) << 2;

    auto issue = [&](int buf, int k0) {
        float* dA = sm + buf * STGW;
        float* dB = dA + OPW;
#pragma unroll
        for (int it = 0; it < 4; it++) {
            int r = lr0 + it * 32;
            cp16(dA + r * STRD + lc4, A + (size_t)(bm + r) * 1024 + k0 + lc4);
            cp16(dB + r * STRD + lc4, W + (size_t)(bn + r) * 1024 + k0 + lc4);
        }
    };

    issue(0, 0);
    asm volatile("cp.async.commit_group;\n" ::: "memory");
    issue(1, BK);
    asm volatile("cp.async.commit_group;\n" ::: "memory");

    for (int t = 0; t < 32; t++) {
        asm volatile("cp.async.wait_group 1;\n" ::: "memory");
        __syncthreads();
        if (t + 2 < 32) issue((t + 2) % NSTG, (t + 2) * BK);
        asm volatile("cp.async.commit_group;\n" ::: "memory");

        const float* As = sm + (t % NSTG) * STGW;
        const float* Bs = As + OPW;
#pragma unroll
        for (int ks = 0; ks < 4; ks++) {
            const int kb = ks * 8;
            unsigned a[2][4], b[8][2];
#pragma unroll
            for (int mi = 0; mi < 2; mi++) {
                int m = wm + mi * 16 + g;
                if (ACVT) {
                    a[mi][0] = f2tf(As[(m)     * STRD + kb + tg]);
                    a[mi][1] = f2tf(As[(m + 8) * STRD + kb + tg]);
                    a[mi][2] = f2tf(As[(m)     * STRD + kb + tg + 4]);
                    a[mi][3] = f2tf(As[(m + 8) * STRD + kb + tg + 4]);
                } else {
                    a[mi][0] = __float_as_uint(As[(m)     * STRD + kb + tg]);
                    a[mi][1] = __float_as_uint(As[(m + 8) * STRD + kb + tg]);
                    a[mi][2] = __float_as_uint(As[(m)     * STRD + kb + tg + 4]);
                    a[mi][3] = __float_as_uint(As[(m + 8) * STRD + kb + tg + 4]);
                }
            }
#pragma unroll
            for (int nj = 0; nj < 8; nj++) {
                int n = wn + nj * 8 + g;
                b[nj][0] = __float_as_uint(Bs[n * STRD + kb + tg]);
                b[nj][1] = __float_as_uint(Bs[n * STRD + kb + tg + 4]);
            }
#pragma unroll
            for (int mi = 0; mi < 2; mi++)
#pragma unroll
                for (int nj = 0; nj < 8; nj++)
                    mma_tf32(acc[mi][nj], a[mi], b[nj]);
        }
    }

#pragma unroll
    for (int mi = 0; mi < 2; mi++) {
#pragma unroll
        for (int nj = 0; nj < 8; nj++) {
            int row0 = bm + wm + mi * 16 + g;
            int col0 = bn + wn + nj * 8 + 2 * tg;
#pragma unroll
            for (int half = 0; half < 2; half++) {
                int row = row0 + half * 8;
                float v0 = acc[mi][nj][half * 2 + 0];
                float v1 = acc[mi][nj][half * 2 + 1];
                if (FMAP) {
                    v0 = (v0 > 0.f) ? (v0 + 1.f) : expf(v0);
                    v1 = (v1 > 0.f) ? (v1 + 1.f) : expf(v1);
                }
                size_t idx;
                if (BHND) {
                    v0 = tf32r(v0); v1 = tf32r(v1);
                    int bb = row >> 11, n = row & 2047;
                    int h = col0 >> 6, d = col0 & 63;
                    idx = ((((size_t)bb * HH + h) * NSEQ + n) * DD + d);
                } else {
                    idx = (size_t)row * 1024 + col0;
                }
                *(float2*)&C[idx] = make_float2(v0, v1);
            }
        }
    }
}

__global__ void __launch_bounds__(256, 2) gemm_qkv(const float* __restrict__ Q,
                                                   const float* __restrict__ K,
                                                   const float* __restrict__ V,
                                                   const float* __restrict__ RW,
                                                   float* __restrict__ qb,
                                                   float* __restrict__ kb,
                                                   float* __restrict__ vb) {
    extern __shared__ float sm[];
    const int z = blockIdx.z;
    const float* A; float* C;
    const float* W = RW + (size_t)z * (EE * EE);
    if (z == 0)      { A = Q; C = qb; }
    else if (z == 1) { A = K; C = kb; }
    else             { A = V; C = vb; }
    if (z < 2) gemm_body<true, true,  true>(A, W, C, sm);
    else       gemm_body<true, false, true>(A, W, C, sm);
}

__global__ void __launch_bounds__(256, 2) gemm_out(const float* __restrict__ A,
                                                   const float* __restrict__ RW,
                                                   float* __restrict__ C) {
    extern __shared__ float sm[];
    gemm_body<false, false, false>(A, RW + (size_t)3 * EE * EE, C, sm);
}

// ---------------------------------------------------------------------------
// Pass 1 (tensor cores): per-chunk ST_c[v][d] = sum_i k[i,d]*v[i,v] (stored
// transposed), z_c[d] = sum_i k[i,d].  64x64x128 mma per chunk, 8 warps (2x4).
// ---------------------------------------------------------------------------
__global__ void __launch_bounds__(256) chunk_kv_tc(const float* __restrict__ k,
                                                   const float* __restrict__ v,
                                                   float* __restrict__ S,
                                                   float* __restrict__ z) {
    extern __shared__ float sm[];
    float* kT = sm;               // [64][132]  k transposed [d][i]
    float* vT = sm + 64 * 132;    // [64][132]  v transposed [d_v][i]
    const int blk = blockIdx.x;
    const int c = blk & 15, bh = blk >> 4;
    const int tid = threadIdx.x;
    const int lane = tid & 31, warp = tid >> 5;
    const int g = lane >> 2, tg = lane & 3;

    const size_t base = ((size_t)bh * NSEQ + (size_t)c * CHK) * DD;
    for (int idx = tid; idx < 2048; idx += 256) {
        int i = idx >> 4, d4 = (idx & 15) << 2;
        float4 kk = *(const float4*)(k + base + (size_t)idx * 4);
        float4 vv = *(const float4*)(v + base + (size_t)idx * 4);
        kT[(d4 + 0) * 132 + i] = kk.x;
        kT[(d4 + 1) * 132 + i] = kk.y;
        kT[(d4 + 2) * 132 + i] = kk.z;
        kT[(d4 + 3) * 132 + i] = kk.w;
        vT[(d4 + 0) * 132 + i] = vv.x;
        vT[(d4 + 1) * 132 + i] = vv.y;
        vT[(d4 + 2) * 132 + i] = vv.z;
        vT[(d4 + 3) * 132 + i] = vv.w;
    }
    __syncthreads();

    // z: 4 lanes per d, each sums 32 i's, butterfly combine
    {
        int d = tid >> 2, quad = tid & 3;
        float s = 0.f;
#pragma unroll
        for (int i = 0; i < 32; i++) s += kT[d * 132 + quad * 32 + i];
        s += __shfl_xor_sync(0xffffffffu, s, 1);
        s += __shfl_xor_sync(0xffffffffu, s, 2);
        if (quad == 0) z[(size_t)blk * 64 + d] = s;
    }

    // D[d][v] = sum_i kT[d][i] * vT[v][i];  warp tile 32x16 (2 m-warps, 4 n-warps)
    const int wm = (warp & 1) * 32, wn = (warp >> 1) * 16;
    float acc[2][2][4];
#pragma unroll
    for (int mi = 0; mi < 2; mi++)
#pragma unroll
        for (int nj = 0; nj < 2; nj++)
#pragma unroll
            for (int x = 0; x < 4; x++) acc[mi][nj][x] = 0.f;

#pragma unroll
    for (int kb = 0; kb < 128; kb += 8) {
        unsigned a[2][4], b[2][2];
#pragma unroll
        for (int mi = 0; mi < 2; mi++) {
            int m = wm + mi * 16 + g;
            a[mi][0] = __float_as_uint(kT[(m)     * 132 + kb + tg]);
            a[mi][1] = __float_as_uint(kT[(m + 8) * 132 + kb + tg]);
            a[mi][2] = __float_as_uint(kT[(m)     * 132 + kb + tg + 4]);
            a[mi][3] = __float_as_uint(kT[(m + 8) * 132 + kb + tg + 4]);
        }
#pragma unroll
        for (int nj = 0; nj < 2; nj++) {
            int n = wn + nj * 8 + g;
            b[nj][0] = __float_as_uint(vT[n * 132 + kb + tg]);
            b[nj][1] = __float_as_uint(vT[n * 132 + kb + tg + 4]);
        }
#pragma unroll
        for (int mi = 0; mi < 2; mi++)
#pragma unroll
            for (int nj = 0; nj < 2; nj++)
                mma_tf32(acc[mi][nj], a[mi], b[nj]);
    }

    // store transposed: ST[v][d] = D[d][v]
    float* Sc = S + (size_t)blk * 4096;
#pragma unroll
    for (int mi = 0; mi < 2; mi++) {
#pragma unroll
        for (int nj = 0; nj < 2; nj++) {
            int d0 = wm + mi * 16 + g;
            int v0 = wn + nj * 8 + 2 * tg;
            Sc[(v0)     * 64 + d0    ] = acc[mi][nj][0];
            Sc[(v0 + 1) * 64 + d0    ] = acc[mi][nj][1];
            Sc[(v0)     * 64 + d0 + 8] = acc[mi][nj][2];
            Sc[(v0 + 1) * 64 + d0 + 8] = acc[mi][nj][3];
        }
    }
}

// ---------------------------------------------------------------------------
// Pass 2: exclusive prefix (causal) / total broadcast. grid (32, 16), blk 256:
// one thread per element -> massive MLP, latency hidden.
// ---------------------------------------------------------------------------
__global__ void __launch_bounds__(256) prefix_k(float* __restrict__ S,
                                                float* __restrict__ z,
                                                const int* __restrict__ causal) {
    const int bh = blockIdx.x;
    const int e = blockIdx.y * 256 + threadIdx.x;
    const int caus = *causal;
    {
        float run = 0.f;
        if (caus) {
            for (int c = 0; c < NCK; c++) {
                size_t idx = ((size_t)bh * NCK + c) * 4096 + e;
                float t = S[idx]; S[idx] = run; run += t;
            }
        } else {
            for (int c = 0; c < NCK; c++) run += S[((size_t)bh * NCK + c) * 4096 + e];
            for (int c = 0; c < NCK; c++) S[((size_t)bh * NCK + c) * 4096 + e] = run;
        }
    }
    if (blockIdx.y == 0 && threadIdx.x < 64) {
        int d = threadIdx.x;
        float run = 0.f;
        if (caus) {
            for (int c = 0; c < NCK; c++) {
                size_t idx = ((size_t)bh * NCK + c) * 64 + d;
                float t = z[idx]; z[idx] = run; run += t;
            }
        } else {
            for (int c = 0; c < NCK; c++) run += z[((size_t)bh * NCK + c) * 64 + d];
            for (int c = 0; c < NCK; c++) z[((size_t)bh * NCK + c) * 64 + d] = run;
        }
    }
}

// ---------------------------------------------------------------------------
// Pass 3 (tensor cores): per-chunk output.  S is stored transposed already.
// ---------------------------------------------------------------------------
__global__ void __launch_bounds__(256) chunk_out_tc(const float* __restrict__ q,
                                                    const float* __restrict__ k,
                                                    const float* __restrict__ v,
                                                    const float* __restrict__ S,
                                                    const float* __restrict__ z,
                                                    const int* __restrict__ causal,
                                                    float* __restrict__ out) {
    extern __shared__ float sm[];
    float* qs  = sm + CO_QS;     // [128][68]
    float* ks  = sm + CO_KS;     // [128][68]
    float* vT  = sm + CO_VT;     // [64][132]
    float* STz = sm + CO_STZ;    // [72][68]  rows 0-63: S^T, row 64: z, 65-71: 0
    float* As  = sm + CO_AS;     // [128][132]

    const int blk = blockIdx.x;
    const int c = blk & 15, bh = blk >> 4;
    const int b = bh >> 4, h = bh & 15;
    const int tid = threadIdx.x;
    const int lane = tid & 31, warp = tid >> 5;
    const int g = lane >> 2, tg = lane & 3;
    const int caus = *causal;
    const int m0 = warp * 16;

    const size_t base = ((size_t)bh * NSEQ + (size_t)c * CHK) * DD;
    for (int idx = tid; idx < 2048; idx += 256) {
        int i = idx >> 4, d4 = (idx & 15) << 2;
        *(float4*)&qs[i * 68 + d4] = *(const float4*)(q + base + (size_t)idx * 4);
        *(float4*)&ks[i * 68 + d4] = *(const float4*)(k + base + (size_t)idx * 4);
        float4 vv = *(const float4*)(v + base + (size_t)idx * 4);
        vT[(d4 + 0) * 132 + i] = vv.x;
        vT[(d4 + 1) * 132 + i] = vv.y;
        vT[(d4 + 2) * 132 + i] = vv.z;
        vT[(d4 + 3) * 132 + i] = vv.w;
    }
    // S already transposed in global: straight float4 copy
    for (int idx = tid; idx < 1024; idx += 256) {
        int j = idx >> 4, d4 = (idx & 15) << 2;
        *(float4*)&STz[j * 68 + d4] =
            *(const float4*)(S + (size_t)blk * 4096 + (size_t)idx * 4);
    }
    if (tid < 64) STz[64 * 68 + tid] = z[(size_t)blk * 64 + tid];
    for (int idx = tid; idx < 7 * 68; idx += 256) STz[65 * 68 + idx] = 0.f;
    __syncthreads();

    const int r0 = m0 + g, r1 = r0 + 8;
    float den0 = 0.f, den1 = 0.f;

    if (caus) {
        float accA[16][4];
#pragma unroll
        for (int nj = 0; nj < 16; nj++)
#pragma unroll
            for (int x = 0; x < 4; x++) accA[nj][x] = 0.f;
#pragma unroll
        for (int kb = 0; kb < 64; kb += 8) {
            unsigned a[4];
            a[0] = __float_as_uint(qs[(r0) * 68 + kb + tg]);
            a[1] = __float_as_uint(qs[(r1) * 68 + kb + tg]);
            a[2] = __float_as_uint(qs[(r0) * 68 + kb + tg + 4]);
            a[3] = __float_as_uint(qs[(r1) * 68 + kb + tg + 4]);
#pragma unroll
            for (int nj = 0; nj < 16; nj++) {
                unsigned bf[2];
                bf[0] = __float_as_uint(ks[(nj * 8 + g) * 68 + kb + tg]);
                bf[1] = __float_as_uint(ks[(nj * 8 + g) * 68 + kb + tg + 4]);
                mma_tf32(accA[nj], a, bf);
            }
        }
#pragma unroll
        for (int nj = 0; nj < 16; nj++) {
            int c0 = nj * 8 + 2 * tg;
            float x00 = (c0     <= r0) ? accA[nj][0] : 0.f;
            float x01 = (c0 + 1 <= r0) ? accA[nj][1] : 0.f;
            float x10 = (c0     <= r1) ? accA[nj][2] : 0.f;
            float x11 = (c0 + 1 <= r1) ? accA[nj][3] : 0.f;
            den0 += x00 + x01;
            den1 += x10 + x11;
            *(float2*)&As[r0 * 132 + c0] = make_float2(x00, x01);
            *(float2*)&As[r1 * 132 + c0] = make_float2(x10, x11);
        }
        den0 += __shfl_xor_sync(0xffffffffu, den0, 1);
        den0 += __shfl_xor_sync(0xffffffffu, den0, 2);
        den1 += __shfl_xor_sync(0xffffffffu, den1, 1);
        den1 += __shfl_xor_sync(0xffffffffu, den1, 2);
        __syncthreads();
    }

    float acc[9][4];
#pragma unroll
    for (int nj = 0; nj < 9; nj++)
#pragma unroll
        for (int x = 0; x < 4; x++) acc[nj][x] = 0.f;

    // q · [S^T | z]  (k-dim = 64)
#pragma unroll
    for (int kb = 0; kb < 64; kb += 8) {
        unsigned a[4];
        a[0] = __float_as_uint(qs[(r0) * 68 + kb + tg]);
        a[1] = __float_as_uint(qs[(r1) * 68 + kb + tg]);
        a[2] = __float_as_uint(qs[(r0) * 68 + kb + tg + 4]);
        a[3] = __float_as_uint(qs[(r1) * 68 + kb + tg + 4]);
#pragma unroll
        for (int nj = 0; nj < 9; nj++) {
            unsigned bf[2];
            bf[0] = f2tf(STz[(nj * 8 + g) * 68 + kb + tg]);
            bf[1] = f2tf(STz[(nj * 8 + g) * 68 + kb + tg + 4]);
            mma_tf32(acc[nj], a, bf);
        }
    }
    // A · v  (k-dim = 128), causal only
    if (caus) {
#pragma unroll
        for (int kb = 0; kb < 128; kb += 8) {
            unsigned a[4];
            a[0] = f2tf(As[(r0) * 132 + kb + tg]);
            a[1] = f2tf(As[(r1) * 132 + kb + tg]);
            a[2] = f2tf(As[(r0) * 132 + kb + tg + 4]);
            a[3] = f2tf(As[(r1) * 132 + kb + tg + 4]);
#pragma unroll
            for (int nj = 0; nj < 8; nj++) {
                unsigned bf[2];
                bf[0] = __float_as_uint(vT[(nj * 8 + g) * 132 + kb + tg]);
                bf[1] = __float_as_uint(vT[(nj * 8 + g) * 132 + kb + tg + 4]);
                mma_tf32(acc[nj], a, bf);
            }
        }
    }

    float qz0 = __shfl_sync(0xffffffffu, acc[8][0], (lane & ~3));
    float qz1 = __shfl_sync(0xffffffffu, acc[8][2], (lane & ~3));
    float inv0 = 1.f / (den0 + qz0 + EPSV);
    float inv1 = 1.f / (den1 + qz1 + EPSV);

#pragma unroll
    for (int nj = 0; nj < 8; nj++) {
        int col = h * 64 + nj * 8 + 2 * tg;
        size_t o0 = ((size_t)b * NSEQ + (size_t)c * CHK + r0) * EE + col;
        size_t o1 = ((size_t)b * NSEQ + (size_t)c * CHK + r1) * EE + col;
        *(float2*)&out[o0] = make_float2(tf32r(acc[nj][0] * inv0), tf32r(acc[nj][1] * inv0));
        *(float2*)&out[o1] = make_float2(tf32r(acc[nj][2] * inv1), tf32r(acc[nj][3] * inv1));
    }
}

// ---------------------------------------------------------------------------
extern "C" void kernel_launch(void* const* d_in, const int* in_sizes, int n_in,
                              void* d_out, int out_size) {
    const float* Q  = (const float*)d_in[0];
    const float* K  = (const float*)d_in[1];
    const float* V  = (const float*)d_in[2];
    const float* Wq = (const float*)d_in[3];
    const float* Wk = (const float*)d_in[4];
    const float* Wv = (const float*)d_in[5];
    const float* Wo = (const float*)d_in[6];
    const int* causal = (const int*)d_in[7];
    float* out = (float*)d_out;

    float *qb, *kb, *vb, *ab, *Sb, *zb, *rw;
    cudaGetSymbolAddress((void**)&qb, g_q);
    cudaGetSymbolAddress((void**)&kb, g_k);
    cudaGetSymbolAddress((void**)&vb, g_v);
    cudaGetSymbolAddress((void**)&ab, g_attn);
    cudaGetSymbolAddress((void**)&Sb, g_S);
    cudaGetSymbolAddress((void**)&zb, g_z);
    cudaGetSymbolAddress((void**)&rw, g_rw);

    cudaFuncSetAttribute(gemm_qkv, cudaFuncAttributeMaxDynamicSharedMemorySize, GSMEM);
    cudaFuncSetAttribute(gemm_out, cudaFuncAttributeMaxDynamicSharedMemorySize, GSMEM);
    cudaFuncSetAttribute(chunk_kv_tc, cudaFuncAttributeMaxDynamicSharedMemorySize, KV_SMEM);
    cudaFuncSetAttribute(chunk_out_tc, cudaFuncAttributeMaxDynamicSharedMemorySize, CO_SMEM);

    round_w<<<dim3(1024, 4), 256>>>(Wq, Wk, Wv, Wo, rw);

    dim3 gq(8, 32, 3);
    gemm_qkv<<<gq, 256, GSMEM>>>(Q, K, V, rw, qb, kb, vb);

    chunk_kv_tc<<<BB * HH * NCK, 256, KV_SMEM>>>(kb, vb, Sb, zb);
    prefix_k<<<dim3(BB * HH, 16), 256>>>(Sb, zb, causal);
    chunk_out_tc<<<BB * HH * NCK, 256, CO_SMEM>>>(qb, kb, vb, Sb, zb, causal, ab);

    dim3 go(8, 32);
    gemm_out<<<go, 256, GSMEM>>>(ab, rw, out);
}

// round 7
// speedup vs baseline: 5.4966x; 1.7033x over previous
#include <cuda_runtime.h>
#include <cuda_fp16.h>
#include <math.h>
#include <stdint.h>

// Problem constants (fixed by setup_inputs)
#define BB    2
#define HH    16
#define NSEQ  2048
#define EE    1024
#define DD    64
#define CHK   128
#define NCK   16
#define EPSV  1e-6f

// fp16 GEMM tiling: 128x128 CTA tile, BK=64 halves, 3-stage cp.async
#define BKH    64
#define SHSTR  72                      // smem row stride in halves (36 words; mod32=4)
#define OP_H   (128 * SHSTR)           // halves per operand per stage (9216)
#define STG_H  (2 * OP_H)              // halves per stage
#define STG_B  (STG_H * 2)             // bytes per stage (36864)
#define NSTG   3
#define GSMEM  (NSTG * STG_B)          // 110592 bytes

// chunk_out smem layout (halves)
#define CO_QS   0                      // [128][72]
#define CO_KS   (CO_QS + 128 * 72)     // [128][72]
#define CO_VT   (CO_KS + 128 * 72)     // [64][136]
#define CO_STZ  (CO_VT + 64 * 136)     // [72][72]
#define CO_AS   (CO_STZ + 72 * 72)     // [128][136]
#define CO_TOT  (CO_AS + 128 * 136)    // 49728 halves
#define CO_SMEM (CO_TOT * 2)           // 99456 bytes

// chunk_kv smem (halves): kT [64][136] + vT [64][136]
#define KV_SMEM (2 * 64 * 136 * 2)     // 34816 bytes

// ---------------- scratch (device globals; no allocation allowed) ----------
__device__ __align__(16) __half g_q[BB*HH*NSEQ*DD];      // features, fp16
__device__ __align__(16) __half g_k[BB*HH*NSEQ*DD];
__device__ __align__(16) __half g_v[BB*HH*NSEQ*DD];
__device__ __align__(16) __half g_attn[BB*NSEQ*EE];      // attention out (B,N,E) fp16
__device__ float g_S[BB*HH*NCK*DD*DD];                   // TRANSPOSED [chunk][v][d], fp32
__device__ float g_z[BB*HH*NCK*DD];                      // fp32
__device__ __align__(16) __half g_wh[4 * EE * EE];       // fp16 Wq,Wk,Wv,Wo
__device__ __align__(16) __half g_xh[3 * BB * NSEQ * EE];// fp16 Q,K,V

// ---------------------------------------------------------------------------
__device__ __forceinline__ void mma_f16(float c[4], const unsigned a[4], const unsigned b[2]) {
    asm volatile(
        "mma.sync.aligned.m16n8k16.row.col.f32.f16.f16.f32 "
        "{%0,%1,%2,%3}, {%4,%5,%6,%7}, {%8,%9}, {%0,%1,%2,%3};\n"
        : "+f"(c[0]), "+f"(c[1]), "+f"(c[2]), "+f"(c[3])
        : "r"(a[0]), "r"(a[1]), "r"(a[2]), "r"(a[3]), "r"(b[0]), "r"(b[1]));
}

__device__ __forceinline__ void cp16s(uint32_t dst, const void* src) {
    asm volatile("cp.async.cg.shared.global [%0], [%1], 16;\n" :: "r"(dst), "l"(src));
}

// ---------------------------------------------------------------------------
// Prepasses: fp32 -> fp16 conversion of weights and inputs.
// ---------------------------------------------------------------------------
__global__ void __launch_bounds__(256) conv_w(const float* __restrict__ w0,
                                              const float* __restrict__ w1,
                                              const float* __restrict__ w2,
                                              const float* __restrict__ w3,
                                              __half* __restrict__ dst) {
    const float* src = (blockIdx.y == 0) ? w0 : (blockIdx.y == 1) ? w1
                       : (blockIdx.y == 2) ? w2 : w3;
    __half* d = dst + (size_t)blockIdx.y * (EE * EE);
    int i = blockIdx.x * 256 + threadIdx.x;
    float4 v = ((const float4*)src)[i];
    __half2 h0 = __floats2half2_rn(v.x, v.y);
    __half2 h1 = __floats2half2_rn(v.z, v.w);
    ((uint2*)d)[i] = make_uint2(*(unsigned*)&h0, *(unsigned*)&h1);
}

__global__ void __launch_bounds__(256) conv_x(const float* __restrict__ x0,
                                              const float* __restrict__ x1,
                                              const float* __restrict__ x2,
                                              __half* __restrict__ dst) {
    const float* src = (blockIdx.y == 0) ? x0 : (blockIdx.y == 1) ? x1 : x2;
    __half* d = dst + (size_t)blockIdx.y * (BB * NSEQ * EE);
    int i = blockIdx.x * 256 + threadIdx.x;
    float4 v = ((const float4*)src)[i];
    __half2 h0 = __floats2half2_rn(v.x, v.y);
    __half2 h1 = __floats2half2_rn(v.z, v.w);
    ((uint2*)d)[i] = make_uint2(*(unsigned*)&h0, *(unsigned*)&h1);
}

// ---------------------------------------------------------------------------
// Pipelined FP16 NT-GEMM: C[m,n] = sum_k A[m,k]*W[n,k], M=4096,N=1024,K=1024.
// A,W fp16 row-K-contiguous. FMAP: elu+1 epilogue. BHND: fp16 out scattered to
// (B,H,N,D); else fp32 out (B,N,E).
// ---------------------------------------------------------------------------
template<bool FMAP, bool BHND>
__device__ __forceinline__ void gemm_h_body(const __half* __restrict__ A,
                                            const __half* __restrict__ W,
                                            void* __restrict__ Cv, __half* sm) {
    const int tid = threadIdx.x, lane = tid & 31, warp = tid >> 5;
    const int bm = blockIdx.y * 128, bn = blockIdx.x * 128;
    const int wm = (warp >> 1) * 32, wn = (warp & 1) * 64;
    const int g = lane >> 2, tg = lane & 3;
    const uint32_t sb = (uint32_t)__cvta_generic_to_shared(sm);

    float acc[2][8][4];
#pragma unroll
    for (int mi = 0; mi < 2; mi++)
#pragma unroll
        for (int nj = 0; nj < 8; nj++)
#pragma unroll
            for (int x = 0; x < 4; x++) acc[mi][nj][x] = 0.f;

    auto issue = [&](int buf, int k0) {
        uint32_t dA = sb + buf * STG_B;
        uint32_t dB = dA + OP_H * 2;
#pragma unroll
        for (int i = 0; i < 4; i++) {
            int l = tid + i * 256;            // 0..1023
            int r = l >> 3, c8 = (l & 7) * 8; // row, half-offset
            uint32_t so = (uint32_t)(r * SHSTR + c8) * 2;
            cp16s(dA + so, A + (size_t)(bm + r) * 1024 + k0 + c8);
            cp16s(dB + so, W + (size_t)(bn + r) * 1024 + k0 + c8);
        }
    };

    issue(0, 0);
    asm volatile("cp.async.commit_group;" ::: "memory");
    issue(1, BKH);
    asm volatile("cp.async.commit_group;" ::: "memory");

    for (int t = 0; t < 16; t++) {
        asm volatile("cp.async.wait_group 1;" ::: "memory");
        __syncthreads();
        if (t + 2 < 16) issue((t + 2) % NSTG, (t + 2) * BKH);
        asm volatile("cp.async.commit_group;" ::: "memory");

        const __half* As = sm + (t % NSTG) * STG_H;
        const __half* Bs = As + OP_H;
#pragma unroll
        for (int ks = 0; ks < 4; ks++) {
            const int kb = ks * 16;
            unsigned a[2][4], b[8][2];
#pragma unroll
            for (int mi = 0; mi < 2; mi++) {
                int m = wm + mi * 16 + g;
                a[mi][0] = *(const unsigned*)&As[(m)     * SHSTR + kb + 2 * tg];
                a[mi][1] = *(const unsigned*)&As[(m + 8) * SHSTR + kb + 2 * tg];
                a[mi][2] = *(const unsigned*)&As[(m)     * SHSTR + kb + 2 * tg + 8];
                a[mi][3] = *(const unsigned*)&As[(m + 8) * SHSTR + kb + 2 * tg + 8];
            }
#pragma unroll
            for (int nj = 0; nj < 8; nj++) {
                int n = wn + nj * 8 + g;
                b[nj][0] = *(const unsigned*)&Bs[n * SHSTR + kb + 2 * tg];
                b[nj][1] = *(const unsigned*)&Bs[n * SHSTR + kb + 2 * tg + 8];
            }
#pragma unroll
            for (int mi = 0; mi < 2; mi++)
#pragma unroll
                for (int nj = 0; nj < 8; nj++)
                    mma_f16(acc[mi][nj], a[mi], b[nj]);
        }
    }

    // epilogue
#pragma unroll
    for (int mi = 0; mi < 2; mi++) {
#pragma unroll
        for (int nj = 0; nj < 8; nj++) {
            int row0 = bm + wm + mi * 16 + g;
            int col0 = bn + wn + nj * 8 + 2 * tg;
#pragma unroll
            for (int half_ = 0; half_ < 2; half_++) {
                int row = row0 + half_ * 8;
                float v0 = acc[mi][nj][half_ * 2 + 0];
                float v1 = acc[mi][nj][half_ * 2 + 1];
                if (FMAP) {
                    v0 = (v0 > 0.f) ? (v0 + 1.f) : expf(v0);
                    v1 = (v1 > 0.f) ? (v1 + 1.f) : expf(v1);
                }
                if (BHND) {
                    int bb = row >> 11, n = row & 2047;
                    int h = col0 >> 6, d = col0 & 63;
                    size_t idx = ((((size_t)bb * HH + h) * NSEQ + n) * DD + d);
                    __half2 hv = __floats2half2_rn(v0, v1);
                    *(__half2*)&((__half*)Cv)[idx] = hv;
                } else {
                    size_t idx = (size_t)row * 1024 + col0;
                    *(float2*)&((float*)Cv)[idx] = make_float2(v0, v1);
                }
            }
        }
    }
}

__global__ void __launch_bounds__(256, 2) gemm_h_qkv(const __half* __restrict__ XH,
                                                     const __half* __restrict__ WH,
                                                     __half* __restrict__ qb,
                                                     __half* __restrict__ kb,
                                                     __half* __restrict__ vb) {
    extern __shared__ __half smh[];
    const int z = blockIdx.z;
    const __half* A = XH + (size_t)z * (BB * NSEQ * EE);
    const __half* W = WH + (size_t)z * (EE * EE);
    __half* C = (z == 0) ? qb : (z == 1) ? kb : vb;
    if (z < 2) gemm_h_body<true,  true>(A, W, C, smh);
    else       gemm_h_body<false, true>(A, W, C, smh);
}

__global__ void __launch_bounds__(256, 2) gemm_h_out(const __half* __restrict__ A,
                                                     const __half* __restrict__ WH,
                                                     float* __restrict__ C) {
    extern __shared__ __half smh[];
    gemm_h_body<false, false>(A, WH + (size_t)3 * EE * EE, C, smh);
}

// ---------------------------------------------------------------------------
// Pass 1 (fp16 mma): ST_c[v][d] = sum_i k[i,d]*v[i,v] (stored transposed, fp32),
// z_c[d] = sum_i k[i,d] (fp32).
// ---------------------------------------------------------------------------
__global__ void __launch_bounds__(256) chunk_kv_h(const __half* __restrict__ k,
                                                  const __half* __restrict__ v,
                                                  float* __restrict__ S,
                                                  float* __restrict__ z) {
    extern __shared__ __half smh[];
    __half* kT = smh;              // [64][136]
    __half* vT = smh + 64 * 136;   // [64][136]
    const int blk = blockIdx.x;
    const int c = blk & 15, bh = blk >> 4;
    const int tid = threadIdx.x;
    const int lane = tid & 31, warp = tid >> 5;
    const int g = lane >> 2, tg = lane & 3;

    const size_t base = ((size_t)bh * NSEQ + (size_t)c * CHK) * DD;
    for (int idx = tid; idx < 1024; idx += 256) {
        int i = idx >> 3, d8 = (idx & 7) * 8;
        uint4 kk = *(const uint4*)&k[base + (size_t)i * 64 + d8];
        uint4 vv = *(const uint4*)&v[base + (size_t)i * 64 + d8];
        const __half* kh = (const __half*)&kk;
        const __half* vh = (const __half*)&vv;
#pragma unroll
        for (int j = 0; j < 8; j++) {
            kT[(d8 + j) * 136 + i] = kh[j];
            vT[(d8 + j) * 136 + i] = vh[j];
        }
    }
    __syncthreads();

    {
        int d = tid >> 2, quad = tid & 3;
        float s = 0.f;
#pragma unroll
        for (int i = 0; i < 32; i++) s += __half2float(kT[d * 136 + quad * 32 + i]);
        s += __shfl_xor_sync(0xffffffffu, s, 1);
        s += __shfl_xor_sync(0xffffffffu, s, 2);
        if (quad == 0) z[(size_t)blk * 64 + d] = s;
    }

    const int wm = (warp & 1) * 32, wn = (warp >> 1) * 16;
    float acc[2][2][4];
#pragma unroll
    for (int mi = 0; mi < 2; mi++)
#pragma unroll
        for (int nj = 0; nj < 2; nj++)
#pragma unroll
            for (int x = 0; x < 4; x++) acc[mi][nj][x] = 0.f;

#pragma unroll
    for (int kb = 0; kb < 128; kb += 16) {
        unsigned a[2][4], b[2][2];
#pragma unroll
        for (int mi = 0; mi < 2; mi++) {
            int m = wm + mi * 16 + g;
            a[mi][0] = *(const unsigned*)&kT[(m)     * 136 + kb + 2 * tg];
            a[mi][1] = *(const unsigned*)&kT[(m + 8) * 136 + kb + 2 * tg];
            a[mi][2] = *(const unsigned*)&kT[(m)     * 136 + kb + 2 * tg + 8];
            a[mi][3] = *(const unsigned*)&kT[(m + 8) * 136 + kb + 2 * tg + 8];
        }
#pragma unroll
        for (int nj = 0; nj < 2; nj++) {
            int n = wn + nj * 8 + g;
            b[nj][0] = *(const unsigned*)&vT[n * 136 + kb + 2 * tg];
            b[nj][1] = *(const unsigned*)&vT[n * 136 + kb + 2 * tg + 8];
        }
#pragma unroll
        for (int mi = 0; mi < 2; mi++)
#pragma unroll
            for (int nj = 0; nj < 2; nj++)
                mma_f16(acc[mi][nj], a[mi], b[nj]);
    }

    float* Sc = S + (size_t)blk * 4096;
#pragma unroll
    for (int mi = 0; mi < 2; mi++) {
#pragma unroll
        for (int nj = 0; nj < 2; nj++) {
            int d0 = wm + mi * 16 + g;
            int v0 = wn + nj * 8 + 2 * tg;
            Sc[(v0)     * 64 + d0    ] = acc[mi][nj][0];
            Sc[(v0 + 1) * 64 + d0    ] = acc[mi][nj][1];
            Sc[(v0)     * 64 + d0 + 8] = acc[mi][nj][2];
            Sc[(v0 + 1) * 64 + d0 + 8] = acc[mi][nj][3];
        }
    }
}

// ---------------------------------------------------------------------------
// Pass 2: exclusive prefix (causal) / total broadcast. fp32. grid (32,16).
// ---------------------------------------------------------------------------
__global__ void __launch_bounds__(256) prefix_k(float* __restrict__ S,
                                                float* __restrict__ z,
                                                const int* __restrict__ causal) {
    const int bh = blockIdx.x;
    const int e = blockIdx.y * 256 + threadIdx.x;
    const int caus = *causal;
    {
        float run = 0.f;
        if (caus) {
            for (int c = 0; c < NCK; c++) {
                size_t idx = ((size_t)bh * NCK + c) * 4096 + e;
                float t = S[idx]; S[idx] = run; run += t;
            }
        } else {
            for (int c = 0; c < NCK; c++) run += S[((size_t)bh * NCK + c) * 4096 + e];
            for (int c = 0; c < NCK; c++) S[((size_t)bh * NCK + c) * 4096 + e] = run;
        }
    }
    if (blockIdx.y == 0 && threadIdx.x < 64) {
        int d = threadIdx.x;
        float run = 0.f;
        if (caus) {
            for (int c = 0; c < NCK; c++) {
                size_t idx = ((size_t)bh * NCK + c) * 64 + d;
                float t = z[idx]; z[idx] = run; run += t;
            }
        } else {
            for (int c = 0; c < NCK; c++) run += z[((size_t)bh * NCK + c) * 64 + d];
            for (int c = 0; c < NCK; c++) z[((size_t)bh * NCK + c) * 64 + d] = run;
        }
    }
}

// ---------------------------------------------------------------------------
// Pass 3 (fp16 mma): per-chunk output -> g_attn (fp16, (B,N,E)).
//   GEMM1: A = tril(q k^T), rowsum via butterfly (fp32), A stored fp16
//   GEMM2: num = q·[S^T|z] + A·v  (z folded as accumulator col 64)
// ---------------------------------------------------------------------------
__global__ void __launch_bounds__(256) chunk_out_h(const __half* __restrict__ q,
                                                   const __half* __restrict__ k,
                                                   const __half* __restrict__ v,
                                                   const float* __restrict__ S,
                                                   const float* __restrict__ z,
                                                   const int* __restrict__ causal,
                                                   __half* __restrict__ out) {
    extern __shared__ __half smh[];
    __half* qs  = smh + CO_QS;    // [128][72]
    __half* ks  = smh + CO_KS;    // [128][72]
    __half* vT  = smh + CO_VT;    // [64][136]
    __half* STz = smh + CO_STZ;   // [72][72]  rows 0-63: S^T, row 64: z, 65-71: 0
    __half* Ash = smh + CO_AS;    // [128][136]

    const int blk = blockIdx.x;
    const int c = blk & 15, bh = blk >> 4;
    const int b = bh >> 4, h = bh & 15;
    const int tid = threadIdx.x;
    const int lane = tid & 31, warp = tid >> 5;
    const int g = lane >> 2, tg = lane & 3;
    const int caus = *causal;
    const int m0 = warp * 16;

    const size_t base = ((size_t)bh * NSEQ + (size_t)c * CHK) * DD;
    for (int idx = tid; idx < 1024; idx += 256) {
        int i = idx >> 3, d8 = (idx & 7) * 8;
        *(uint4*)&qs[i * 72 + d8] = *(const uint4*)&q[base + (size_t)i * 64 + d8];
        *(uint4*)&ks[i * 72 + d8] = *(const uint4*)&k[base + (size_t)i * 64 + d8];
        uint4 vv = *(const uint4*)&v[base + (size_t)i * 64 + d8];
        const __half* vh = (const __half*)&vv;
#pragma unroll
        for (int j = 0; j < 8; j++) vT[(d8 + j) * 136 + i] = vh[j];
    }
    // S^T (fp32 global, already [v][d]) -> fp16 smem
    const float* Sg = S + (size_t)blk * 4096;
    for (int idx = tid; idx < 512; idx += 256) {
        int j = idx >> 3, d8 = (idx & 7) * 8;
        float4 s0 = *(const float4*)&Sg[j * 64 + d8];
        float4 s1 = *(const float4*)&Sg[j * 64 + d8 + 4];
        __half2 h0 = __floats2half2_rn(s0.x, s0.y);
        __half2 h1 = __floats2half2_rn(s0.z, s0.w);
        __half2 h2 = __floats2half2_rn(s1.x, s1.y);
        __half2 h3 = __floats2half2_rn(s1.z, s1.w);
        uint4 pk = make_uint4(*(unsigned*)&h0, *(unsigned*)&h1,
                              *(unsigned*)&h2, *(unsigned*)&h3);
        *(uint4*)&STz[j * 72 + d8] = pk;
    }
    if (tid < 64) STz[64 * 72 + tid] = __float2half_rn(z[(size_t)blk * 64 + tid]);
    for (int idx = tid; idx < 7 * 72; idx += 256) STz[65 * 72 + idx] = __float2half_rn(0.f);
    __syncthreads();

    const int r0 = m0 + g, r1 = r0 + 8;
    float den0 = 0.f, den1 = 0.f;

    if (caus) {
        float accA[16][4];
#pragma unroll
        for (int nj = 0; nj < 16; nj++)
#pragma unroll
            for (int x = 0; x < 4; x++) accA[nj][x] = 0.f;
#pragma unroll
        for (int kb = 0; kb < 64; kb += 16) {
            unsigned a[4];
            a[0] = *(const unsigned*)&qs[(r0) * 72 + kb + 2 * tg];
            a[1] = *(const unsigned*)&qs[(r1) * 72 + kb + 2 * tg];
            a[2] = *(const unsigned*)&qs[(r0) * 72 + kb + 2 * tg + 8];
            a[3] = *(const unsigned*)&qs[(r1) * 72 + kb + 2 * tg + 8];
#pragma unroll
            for (int nj = 0; nj < 16; nj++) {
                unsigned bf[2];
                bf[0] = *(const unsigned*)&ks[(nj * 8 + g) * 72 + kb + 2 * tg];
                bf[1] = *(const unsigned*)&ks[(nj * 8 + g) * 72 + kb + 2 * tg + 8];
                mma_f16(accA[nj], a, bf);
            }
        }
#pragma unroll
        for (int nj = 0; nj < 16; nj++) {
            int c0 = nj * 8 + 2 * tg;
            float x00 = (c0     <= r0) ? accA[nj][0] : 0.f;
            float x01 = (c0 + 1 <= r0) ? accA[nj][1] : 0.f;
            float x10 = (c0     <= r1) ? accA[nj][2] : 0.f;
            float x11 = (c0 + 1 <= r1) ? accA[nj][3] : 0.f;
            den0 += x00 + x01;
            den1 += x10 + x11;
            *(__half2*)&Ash[r0 * 136 + c0] = __floats2half2_rn(x00, x01);
            *(__half2*)&Ash[r1 * 136 + c0] = __floats2half2_rn(x10, x11);
        }
        den0 += __shfl_xor_sync(0xffffffffu, den0, 1);
        den0 += __shfl_xor_sync(0xffffffffu, den0, 2);
        den1 += __shfl_xor_sync(0xffffffffu, den1, 1);
        den1 += __shfl_xor_sync(0xffffffffu, den1, 2);
        __syncthreads();
    }

    float acc[9][4];
#pragma unroll
    for (int nj = 0; nj < 9; nj++)
#pragma unroll
        for (int x = 0; x < 4; x++) acc[nj][x] = 0.f;

    // q · [S^T | z]  (k-dim = 64)
#pragma unroll
    for (int kb = 0; kb < 64; kb += 16) {
        unsigned a[4];
        a[0] = *(const unsigned*)&qs[(r0) * 72 + kb + 2 * tg];
        a[1] = *(const unsigned*)&qs[(r1) * 72 + kb + 2 * tg];
        a[2] = *(const unsigned*)&qs[(r0) * 72 + kb + 2 * tg + 8];
        a[3] = *(const unsigned*)&qs[(r1) * 72 + kb + 2 * tg + 8];
#pragma unroll
        for (int nj = 0; nj < 9; nj++) {
            unsigned bf[2];
            bf[0] = *(const unsigned*)&STz[(nj * 8 + g) * 72 + kb + 2 * tg];
            bf[1] = *(const unsigned*)&STz[(nj * 8 + g) * 72 + kb + 2 * tg + 8];
            mma_f16(acc[nj], a, bf);
        }
    }
    // A · v  (k-dim = 128), causal only
    if (caus) {
#pragma unroll
        for (int kb = 0; kb < 128; kb += 16) {
            unsigned a[4];
            a[0] = *(const unsigned*)&Ash[(r0) * 136 + kb + 2 * tg];
            a[1] = *(const unsigned*)&Ash[(r1) * 136 + kb + 2 * tg];
            a[2] = *(const unsigned*)&Ash[(r0) * 136 + kb + 2 * tg + 8];
            a[3] = *(const unsigned*)&Ash[(r1) * 136 + kb + 2 * tg + 8];
#pragma unroll
            for (int nj = 0; nj < 8; nj++) {
                unsigned bf[2];
                bf[0] = *(const unsigned*)&vT[(nj * 8 + g) * 136 + kb + 2 * tg];
                bf[1] = *(const unsigned*)&vT[(nj * 8 + g) * 136 + kb + 2 * tg + 8];
                mma_f16(acc[nj], a, bf);
            }
        }
    }

    float qz0 = __shfl_sync(0xffffffffu, acc[8][0], (lane & ~3));
    float qz1 = __shfl_sync(0xffffffffu, acc[8][2], (lane & ~3));
    float inv0 = 1.f / (den0 + qz0 + EPSV);
    float inv1 = 1.f / (den1 + qz1 + EPSV);

#pragma unroll
    for (int nj = 0; nj < 8; nj++) {
        int col = h * 64 + nj * 8 + 2 * tg;
        size_t o0 = ((size_t)b * NSEQ + (size_t)c * CHK + r0) * EE + col;
        size_t o1 = ((size_t)b * NSEQ + (size_t)c * CHK + r1) * EE + col;
        *(__half2*)&out[o0] = __floats2half2_rn(acc[nj][0] * inv0, acc[nj][1] * inv0);
        *(__half2*)&out[o1] = __floats2half2_rn(acc[nj][2] * inv1, acc[nj][3] * inv1);
    }
}

// ---------------------------------------------------------------------------
extern "C" void kernel_launch(void* const* d_in, const int* in_sizes, int n_in,
                              void* d_out, int out_size) {
    const float* Q  = (const float*)d_in[0];
    const float* K  = (const float*)d_in[1];
    const float* V  = (const float*)d_in[2];
    const float* Wq = (const float*)d_in[3];
    const float* Wk = (const float*)d_in[4];
    const float* Wv = (const float*)d_in[5];
    const float* Wo = (const float*)d_in[6];
    const int* causal = (const int*)d_in[7];
    float* out = (float*)d_out;

    __half *qb, *kb, *vb, *ab, *wh, *xh;
    float *Sb, *zb;
    cudaGetSymbolAddress((void**)&qb, g_q);
    cudaGetSymbolAddress((void**)&kb, g_k);
    cudaGetSymbolAddress((void**)&vb, g_v);
    cudaGetSymbolAddress((void**)&ab, g_attn);
    cudaGetSymbolAddress((void**)&Sb, g_S);
    cudaGetSymbolAddress((void**)&zb, g_z);
    cudaGetSymbolAddress((void**)&wh, g_wh);
    cudaGetSymbolAddress((void**)&xh, g_xh);

    cudaFuncSetAttribute(gemm_h_qkv, cudaFuncAttributeMaxDynamicSharedMemorySize, GSMEM);
    cudaFuncSetAttribute(gemm_h_out, cudaFuncAttributeMaxDynamicSharedMemorySize, GSMEM);
    cudaFuncSetAttribute(chunk_kv_h, cudaFuncAttributeMaxDynamicSharedMemorySize, KV_SMEM);
    cudaFuncSetAttribute(chunk_out_h, cudaFuncAttributeMaxDynamicSharedMemorySize, CO_SMEM);

    conv_w<<<dim3(1024, 4), 256>>>(Wq, Wk, Wv, Wo, wh);
    conv_x<<<dim3(4096, 3), 256>>>(Q, K, V, xh);

    dim3 gq(8, 32, 3);
    gemm_h_qkv<<<gq, 256, GSMEM>>>(xh, wh, qb, kb, vb);

    chunk_kv_h<<<BB * HH * NCK, 256, KV_SMEM>>>(kb, vb, Sb, zb);
    prefix_k<<<dim3(BB * HH, 16), 256>>>(Sb, zb, causal);
    chunk_out_h<<<BB * HH * NCK, 256, CO_SMEM>>>(qb, kb, vb, Sb, zb, causal, ab);

    dim3 go(8, 32);
    gemm_h_out<<<go, 256, GSMEM>>>(ab, wh, out);
}

// round 9
// speedup vs baseline: 5.6716x; 1.0319x over previous
#include <cuda_runtime.h>
#include <cuda_fp16.h>
#include <math.h>
#include <stdint.h>

// Problem constants (fixed by setup_inputs)
#define BB    2
#define HH    16
#define NSEQ  2048
#define EE    1024
#define DD    64
#define CHK   128
#define NCK   16
#define EPSV  1e-6f

// fp16 GEMM tiling: 128x128 CTA tile, BK=64 halves, 3-stage cp.async
#define BKH    64
#define SHSTR  72
#define OP_H   (128 * SHSTR)
#define STG_H  (2 * OP_H)
#define STG_B  (STG_H * 2)
#define NSTG   3
#define GSMEM  (NSTG * STG_B)          // 110592 bytes

// chunk_out smem layout (halves)
#define CO_QS   0                      // [128][72]
#define CO_KS   (CO_QS + 128 * 72)     // [128][72]
#define CO_VT   (CO_KS + 128 * 72)     // [64][136] swizzled
#define CO_STZ  (CO_VT + 64 * 136)     // [72][72]
#define CO_AS   (CO_STZ + 72 * 72)     // [128][136]
#define CO_TOT  (CO_AS + 128 * 136)
#define CO_SMEM (CO_TOT * 2)           // 99456 bytes

// chunk_kv smem (halves): kT [64][136] + vT [64][136], swizzled
#define KV_SMEM (2 * 64 * 136 * 2)

// ---------------- scratch (device globals; no allocation allowed) ----------
__device__ __align__(16) __half g_q[BB*HH*NSEQ*DD];
__device__ __align__(16) __half g_k[BB*HH*NSEQ*DD];
__device__ __align__(16) __half g_v[BB*HH*NSEQ*DD];
__device__ __align__(16) __half g_attn[BB*NSEQ*EE];
__device__ float g_S[BB*HH*NCK*DD*DD];                    // per-chunk KtV, [v][d] fp32
__device__ __align__(16) __half g_Sh[BB*HH*NCK*DD*DD];    // prefixed, fp16
__device__ float g_z[BB*HH*NCK*DD];
__device__ __align__(16) __half g_zh[BB*HH*NCK*DD];
__device__ __align__(16) __half g_wh[4 * EE * EE];
__device__ __align__(16) __half g_xh[3 * BB * NSEQ * EE];

// ---------------------------------------------------------------------------
__device__ __forceinline__ void mma_f16(float c[4], const unsigned a[4], const unsigned b[2]) {
    asm volatile(
        "mma.sync.aligned.m16n8k16.row.col.f32.f16.f16.f32 "
        "{%0,%1,%2,%3}, {%4,%5,%6,%7}, {%8,%9}, {%0,%1,%2,%3};\n"
        : "+f"(c[0]), "+f"(c[1]), "+f"(c[2]), "+f"(c[3])
        : "r"(a[0]), "r"(a[1]), "r"(a[2]), "r"(a[3]), "r"(b[0]), "r"(b[1]));
}

__device__ __forceinline__ void cp16s(uint32_t dst, const void* src) {
    asm volatile("cp.async.cg.shared.global [%0], [%1], 16;\n" :: "r"(dst), "l"(src));
}

// swizzled half index into a [64][136] transposed tile: row d, half-col i
__device__ __forceinline__ int swz136(int d, int i) {
    return d * 136 + (((((i >> 1) ^ ((d >> 3) & 7))) << 1) | (i & 1));
}
// word-aligned variant: row d, word wi (2 halves)
__device__ __forceinline__ int swz136w(int d, int wi) {
    return d * 136 + (((wi) ^ ((d >> 3) & 7)) << 1);
}

// ---------------------------------------------------------------------------
// Fused prepass: fp32 -> fp16 for 4 weights (z=0..3) and 3 inputs (z=4..6).
// grid (4096, 7); weights use only first 1024 x-blocks (1M floats each),
// inputs use all 4096 (4M floats each).
// ---------------------------------------------------------------------------
__global__ void __launch_bounds__(256) conv_all(const float* __restrict__ w0,
                                                const float* __restrict__ w1,
                                                const float* __restrict__ w2,
                                                const float* __restrict__ w3,
                                                const float* __restrict__ x0,
                                                const float* __restrict__ x1,
                                                const float* __restrict__ x2,
                                                __half* __restrict__ wdst,
                                                __half* __restrict__ xdst) {
    const int z = blockIdx.y;
    const float* src;
    __half* d;
    if (z < 4) {
        if (blockIdx.x >= 1024) return;
        src = (z == 0) ? w0 : (z == 1) ? w1 : (z == 2) ? w2 : w3;
        d = wdst + (size_t)z * (EE * EE);
    } else {
        src = (z == 4) ? x0 : (z == 5) ? x1 : x2;
        d = xdst + (size_t)(z - 4) * (BB * NSEQ * EE);
    }
    int i = blockIdx.x * 256 + threadIdx.x;
    float4 v = ((const float4*)src)[i];
    __half2 h0 = __floats2half2_rn(v.x, v.y);
    __half2 h1 = __floats2half2_rn(v.z, v.w);
    ((uint2*)d)[i] = make_uint2(*(unsigned*)&h0, *(unsigned*)&h1);
}

// ---------------------------------------------------------------------------
// Pipelined FP16 NT-GEMM.
// ---------------------------------------------------------------------------
template<bool FMAP, bool BHND>
__device__ __forceinline__ void gemm_h_body(const __half* __restrict__ A,
                                            const __half* __restrict__ W,
                                            void* __restrict__ Cv, __half* sm) {
    const int tid = threadIdx.x, lane = tid & 31, warp = tid >> 5;
    const int bm = blockIdx.y * 128, bn = blockIdx.x * 128;
    const int wm = (warp >> 1) * 32, wn = (warp & 1) * 64;
    const int g = lane >> 2, tg = lane & 3;
    const uint32_t sb = (uint32_t)__cvta_generic_to_shared(sm);

    float acc[2][8][4];
#pragma unroll
    for (int mi = 0; mi < 2; mi++)
#pragma unroll
        for (int nj = 0; nj < 8; nj++)
#pragma unroll
            for (int x = 0; x < 4; x++) acc[mi][nj][x] = 0.f;

    auto issue = [&](int buf, int k0) {
        uint32_t dA = sb + buf * STG_B;
        uint32_t dB = dA + OP_H * 2;
#pragma unroll
        for (int i = 0; i < 4; i++) {
            int l = tid + i * 256;
            int r = l >> 3, c8 = (l & 7) * 8;
            uint32_t so = (uint32_t)(r * SHSTR + c8) * 2;
            cp16s(dA + so, A + (size_t)(bm + r) * 1024 + k0 + c8);
            cp16s(dB + so, W + (size_t)(bn + r) * 1024 + k0 + c8);
        }
    };

    issue(0, 0);
    asm volatile("cp.async.commit_group;" ::: "memory");
    issue(1, BKH);
    asm volatile("cp.async.commit_group;" ::: "memory");

    for (int t = 0; t < 16; t++) {
        asm volatile("cp.async.wait_group 1;" ::: "memory");
        __syncthreads();
        if (t + 2 < 16) issue((t + 2) % NSTG, (t + 2) * BKH);
        asm volatile("cp.async.commit_group;" ::: "memory");

        const __half* As = sm + (t % NSTG) * STG_H;
        const __half* Bs = As + OP_H;
#pragma unroll
        for (int ks = 0; ks < 4; ks++) {
            const int kb = ks * 16;
            unsigned a[2][4], b[8][2];
#pragma unroll
            for (int mi = 0; mi < 2; mi++) {
                int m = wm + mi * 16 + g;
                a[mi][0] = *(const unsigned*)&As[(m)     * SHSTR + kb + 2 * tg];
                a[mi][1] = *(const unsigned*)&As[(m + 8) * SHSTR + kb + 2 * tg];
                a[mi][2] = *(const unsigned*)&As[(m)     * SHSTR + kb + 2 * tg + 8];
                a[mi][3] = *(const unsigned*)&As[(m + 8) * SHSTR + kb + 2 * tg + 8];
            }
#pragma unroll
            for (int nj = 0; nj < 8; nj++) {
                int n = wn + nj * 8 + g;
                b[nj][0] = *(const unsigned*)&Bs[n * SHSTR + kb + 2 * tg];
                b[nj][1] = *(const unsigned*)&Bs[n * SHSTR + kb + 2 * tg + 8];
            }
#pragma unroll
            for (int mi = 0; mi < 2; mi++)
#pragma unroll
                for (int nj = 0; nj < 8; nj++)
                    mma_f16(acc[mi][nj], a[mi], b[nj]);
        }
    }

#pragma unroll
    for (int mi = 0; mi < 2; mi++) {
#pragma unroll
        for (int nj = 0; nj < 8; nj++) {
            int row0 = bm + wm + mi * 16 + g;
            int col0 = bn + wn + nj * 8 + 2 * tg;
#pragma unroll
            for (int half_ = 0; half_ < 2; half_++) {
                int row = row0 + half_ * 8;
                float v0 = acc[mi][nj][half_ * 2 + 0];
                float v1 = acc[mi][nj][half_ * 2 + 1];
                if (FMAP) {
                    v0 = (v0 > 0.f) ? (v0 + 1.f) : expf(v0);
                    v1 = (v1 > 0.f) ? (v1 + 1.f) : expf(v1);
                }
                if (BHND) {
                    int bb = row >> 11, n = row & 2047;
                    int h = col0 >> 6, d = col0 & 63;
                    size_t idx = ((((size_t)bb * HH + h) * NSEQ + n) * DD + d);
                    __half2 hv = __floats2half2_rn(v0, v1);
                    *(__half2*)&((__half*)Cv)[idx] = hv;
                } else {
                    size_t idx = (size_t)row * 1024 + col0;
                    *(float2*)&((float*)Cv)[idx] = make_float2(v0, v1);
                }
            }
        }
    }
}

__global__ void __launch_bounds__(256, 2) gemm_h_qkv(const __half* __restrict__ XH,
                                                     const __half* __restrict__ WH,
                                                     __half* __restrict__ qb,
                                                     __half* __restrict__ kb,
                                                     __half* __restrict__ vb) {
    extern __shared__ __half smh[];
    const int z = blockIdx.z;
    const __half* A = XH + (size_t)z * (BB * NSEQ * EE);
    const __half* W = WH + (size_t)z * (EE * EE);
    __half* C = (z == 0) ? qb : (z == 1) ? kb : vb;
    if (z < 2) gemm_h_body<true,  true>(A, W, C, smh);
    else       gemm_h_body<false, true>(A, W, C, smh);
}

__global__ void __launch_bounds__(256, 2) gemm_h_out(const __half* __restrict__ A,
                                                     const __half* __restrict__ WH,
                                                     float* __restrict__ C) {
    extern __shared__ __half smh[];
    gemm_h_body<false, false>(A, WH + (size_t)3 * EE * EE, C, smh);
}

// ---------------------------------------------------------------------------
// Pass 1 (fp16 mma): ST_c[v][d] = sum_i k[i,d]*v[i,v] (fp32, transposed),
// z_c[d] = sum_i k[i,d]. Swizzled smem transposes (conflict-free).
// ---------------------------------------------------------------------------
__global__ void __launch_bounds__(256) chunk_kv_h(const __half* __restrict__ k,
                                                  const __half* __restrict__ v,
                                                  float* __restrict__ S,
                                                  float* __restrict__ z) {
    extern __shared__ __half smh[];
    __half* kT = smh;              // [64][136] swizzled
    __half* vT = smh + 64 * 136;
    const int blk = blockIdx.x;
    const int c = blk & 15, bh = blk >> 4;
    const int tid = threadIdx.x;
    const int lane = tid & 31, warp = tid >> 5;
    const int g = lane >> 2, tg = lane & 3;

    const size_t base = ((size_t)bh * NSEQ + (size_t)c * CHK) * DD;
    for (int idx = tid; idx < 1024; idx += 256) {
        int i = idx >> 3, d8 = (idx & 7) * 8;
        uint4 kk = *(const uint4*)&k[base + (size_t)i * 64 + d8];
        uint4 vv = *(const uint4*)&v[base + (size_t)i * 64 + d8];
        const __half* kh = (const __half*)&kk;
        const __half* vh = (const __half*)&vv;
#pragma unroll
        for (int j = 0; j < 8; j++) {
            kT[swz136(d8 + j, i)] = kh[j];
            vT[swz136(d8 + j, i)] = vh[j];
        }
    }
    __syncthreads();

    // z: 4 lanes per d, word loads
    {
        int d = tid >> 2, quad = tid & 3;
        float s = 0.f;
#pragma unroll
        for (int wi = 0; wi < 16; wi++) {
            unsigned u = *(const unsigned*)&kT[swz136w(d, quad * 16 + wi)];
            __half2 h = *(__half2*)&u;
            s += __half2float(h.x) + __half2float(h.y);
        }
        s += __shfl_xor_sync(0xffffffffu, s, 1);
        s += __shfl_xor_sync(0xffffffffu, s, 2);
        if (quad == 0) z[(size_t)blk * 64 + d] = s;
    }

    const int wm = (warp & 1) * 32, wn = (warp >> 1) * 16;
    float acc[2][2][4];
#pragma unroll
    for (int mi = 0; mi < 2; mi++)
#pragma unroll
        for (int nj = 0; nj < 2; nj++)
#pragma unroll
            for (int x = 0; x < 4; x++) acc[mi][nj][x] = 0.f;

#pragma unroll
    for (int kb = 0; kb < 128; kb += 16) {
        const int w0 = kb >> 1;    // word base
        unsigned a[2][4], b[2][2];
#pragma unroll
        for (int mi = 0; mi < 2; mi++) {
            int m = wm + mi * 16 + g;
            a[mi][0] = *(const unsigned*)&kT[swz136w(m,     w0 + tg)];
            a[mi][1] = *(const unsigned*)&kT[swz136w(m + 8, w0 + tg)];
            a[mi][2] = *(const unsigned*)&kT[swz136w(m,     w0 + tg + 4)];
            a[mi][3] = *(const unsigned*)&kT[swz136w(m + 8, w0 + tg + 4)];
        }
#pragma unroll
        for (int nj = 0; nj < 2; nj++) {
            int n = wn + nj * 8 + g;
            b[nj][0] = *(const unsigned*)&vT[swz136w(n, w0 + tg)];
            b[nj][1] = *(const unsigned*)&vT[swz136w(n, w0 + tg + 4)];
        }
#pragma unroll
        for (int mi = 0; mi < 2; mi++)
#pragma unroll
            for (int nj = 0; nj < 2; nj++)
                mma_f16(acc[mi][nj], a[mi], b[nj]);
    }

    float* Sc = S + (size_t)blk * 4096;
#pragma unroll
    for (int mi = 0; mi < 2; mi++) {
#pragma unroll
        for (int nj = 0; nj < 2; nj++) {
            int d0 = wm + mi * 16 + g;
            int v0 = wn + nj * 8 + 2 * tg;
            Sc[(v0)     * 64 + d0    ] = acc[mi][nj][0];
            Sc[(v0 + 1) * 64 + d0    ] = acc[mi][nj][1];
            Sc[(v0)     * 64 + d0 + 8] = acc[mi][nj][2];
            Sc[(v0 + 1) * 64 + d0 + 8] = acc[mi][nj][3];
        }
    }
}

// ---------------------------------------------------------------------------
// Pass 2: exclusive prefix (causal) / total (non-causal); fp32 scan in regs,
// fp16 output for chunk_out. grid (32,16).
// ---------------------------------------------------------------------------
__global__ void __launch_bounds__(256) prefix_k(const float* __restrict__ S,
                                                const float* __restrict__ z,
                                                __half* __restrict__ Sh,
                                                __half* __restrict__ zh,
                                                const int* __restrict__ causal) {
    const int bh = blockIdx.x;
    const int e = blockIdx.y * 256 + threadIdx.x;
    const int caus = *causal;
    {
        float run = 0.f;
        if (caus) {
            for (int c = 0; c < NCK; c++) {
                size_t idx = ((size_t)bh * NCK + c) * 4096 + e;
                Sh[idx] = __float2half_rn(run);
                run += S[idx];
            }
        } else {
            for (int c = 0; c < NCK; c++) run += S[((size_t)bh * NCK + c) * 4096 + e];
            __half hr = __float2half_rn(run);
            for (int c = 0; c < NCK; c++) Sh[((size_t)bh * NCK + c) * 4096 + e] = hr;
        }
    }
    if (blockIdx.y == 0 && threadIdx.x < 64) {
        int d = threadIdx.x;
        float run = 0.f;
        if (caus) {
            for (int c = 0; c < NCK; c++) {
                size_t idx = ((size_t)bh * NCK + c) * 64 + d;
                zh[idx] = __float2half_rn(run);
                run += z[idx];
            }
        } else {
            for (int c = 0; c < NCK; c++) run += z[((size_t)bh * NCK + c) * 64 + d];
            __half hr = __float2half_rn(run);
            for (int c = 0; c < NCK; c++) zh[((size_t)bh * NCK + c) * 64 + d] = hr;
        }
    }
}

// ---------------------------------------------------------------------------
// Pass 3 (fp16 mma): per-chunk output. Triangular skips + swizzled vT.
// ---------------------------------------------------------------------------
__global__ void __launch_bounds__(256) chunk_out_h(const __half* __restrict__ q,
                                                   const __half* __restrict__ k,
                                                   const __half* __restrict__ v,
                                                   const __half* __restrict__ Sh,
                                                   const __half* __restrict__ zh,
                                                   const int* __restrict__ causal,
                                                   __half* __restrict__ out) {
    extern __shared__ __half smh[];
    __half* qs  = smh + CO_QS;    // [128][72]
    __half* ks  = smh + CO_KS;    // [128][72]
    __half* vT  = smh + CO_VT;    // [64][136] swizzled
    __half* STz = smh + CO_STZ;   // [72][72]
    __half* Ash = smh + CO_AS;    // [128][136]

    const int blk = blockIdx.x;
    const int c = blk & 15, bh = blk >> 4;
    const int b = bh >> 4, h = bh & 15;
    const int tid = threadIdx.x;
    const int lane = tid & 31, warp = tid >> 5;
    const int g = lane >> 2, tg = lane & 3;
    const int caus = *causal;
    const int m0 = warp * 16;

    const size_t base = ((size_t)bh * NSEQ + (size_t)c * CHK) * DD;
    for (int idx = tid; idx < 1024; idx += 256) {
        int i = idx >> 3, d8 = (idx & 7) * 8;
        *(uint4*)&qs[i * 72 + d8] = *(const uint4*)&q[base + (size_t)i * 64 + d8];
        *(uint4*)&ks[i * 72 + d8] = *(const uint4*)&k[base + (size_t)i * 64 + d8];
        uint4 vv = *(const uint4*)&v[base + (size_t)i * 64 + d8];
        const __half* vh = (const __half*)&vv;
#pragma unroll
        for (int j = 0; j < 8; j++) vT[swz136(d8 + j, i)] = vh[j];
    }
    // STz rows 0-63 = S^T (fp16 in global already)
    for (int idx = tid; idx < 512; idx += 256) {
        int j = idx >> 3, d8 = (idx & 7) * 8;
        *(uint4*)&STz[j * 72 + d8] =
            *(const uint4*)&Sh[(size_t)blk * 4096 + (size_t)j * 64 + d8];
    }
    if (tid < 64) STz[64 * 72 + tid] = zh[(size_t)blk * 64 + tid];
    for (int idx = tid; idx < 7 * 72; idx += 256) STz[65 * 72 + idx] = __float2half_rn(0.f);
    __syncthreads();

    const int r0 = m0 + g, r1 = r0 + 8;
    float den0 = 0.f, den1 = 0.f;

    if (caus) {
        const int njmax = 2 * warp + 1;    // tiles nj > njmax are all-zero
#pragma unroll
        for (int h2 = 0; h2 < 2; h2++) {
            if (h2 * 8 <= njmax) {
                float accA[8][4];
#pragma unroll
                for (int nj = 0; nj < 8; nj++)
#pragma unroll
                    for (int x = 0; x < 4; x++) accA[nj][x] = 0.f;
#pragma unroll
                for (int kb = 0; kb < 64; kb += 16) {
                    unsigned a[4];
                    a[0] = *(const unsigned*)&qs[(r0) * 72 + kb + 2 * tg];
                    a[1] = *(const unsigned*)&qs[(r1) * 72 + kb + 2 * tg];
                    a[2] = *(const unsigned*)&qs[(r0) * 72 + kb + 2 * tg + 8];
                    a[3] = *(const unsigned*)&qs[(r1) * 72 + kb + 2 * tg + 8];
#pragma unroll
                    for (int nj = 0; nj < 8; nj++) {
                        int njg = h2 * 8 + nj;
                        if (njg <= njmax) {
                            unsigned bf[2];
                            bf[0] = *(const unsigned*)&ks[(njg * 8 + g) * 72 + kb + 2 * tg];
                            bf[1] = *(const unsigned*)&ks[(njg * 8 + g) * 72 + kb + 2 * tg + 8];
                            mma_f16(accA[nj], a, bf);
                        }
                    }
                }
#pragma unroll
                for (int nj = 0; nj < 8; nj++) {
                    int njg = h2 * 8 + nj;
                    if (njg <= njmax) {
                        int c0 = njg * 8 + 2 * tg;
                        float x00 = (c0     <= r0) ? accA[nj][0] : 0.f;
                        float x01 = (c0 + 1 <= r0) ? accA[nj][1] : 0.f;
                        float x10 = (c0     <= r1) ? accA[nj][2] : 0.f;
                        float x11 = (c0 + 1 <= r1) ? accA[nj][3] : 0.f;
                        den0 += x00 + x01;
                        den1 += x10 + x11;
                        *(__half2*)&Ash[r0 * 136 + c0] = __floats2half2_rn(x00, x01);
                        *(__half2*)&Ash[r1 * 136 + c0] = __floats2half2_rn(x10, x11);
                    }
                }
            }
        }
        den0 += __shfl_xor_sync(0xffffffffu, den0, 1);
        den0 += __shfl_xor_sync(0xffffffffu, den0, 2);
        den1 += __shfl_xor_sync(0xffffffffu, den1, 1);
        den1 += __shfl_xor_sync(0xffffffffu, den1, 2);
        __syncwarp();   // Ash rows are warp-private
    }

    float acc[9][4];
#pragma unroll
    for (int nj = 0; nj < 9; nj++)
#pragma unroll
        for (int x = 0; x < 4; x++) acc[nj][x] = 0.f;

    // q · [S^T | z]  (k-dim = 64)
#pragma unroll
    for (int kb = 0; kb < 64; kb += 16) {
        unsigned a[4];
        a[0] = *(const unsigned*)&qs[(r0) * 72 + kb + 2 * tg];
        a[1] = *(const unsigned*)&qs[(r1) * 72 + kb + 2 * tg];
        a[2] = *(const unsigned*)&qs[(r0) * 72 + kb + 2 * tg + 8];
        a[3] = *(const unsigned*)&qs[(r1) * 72 + kb + 2 * tg + 8];
#pragma unroll
        for (int nj = 0; nj < 9; nj++) {
            unsigned bf[2];
            bf[0] = *(const unsigned*)&STz[(nj * 8 + g) * 72 + kb + 2 * tg];
            bf[1] = *(const unsigned*)&STz[(nj * 8 + g) * 72 + kb + 2 * tg + 8];
            mma_f16(acc[nj], a, bf);
        }
    }
    // A · v  (k-dim = 128): A cols > m0+15 are zero -> only k-tiles kb/16 <= warp
    if (caus) {
#pragma unroll
        for (int kb = 0; kb < 128; kb += 16) {
            if ((kb >> 4) <= warp) {
                const int w0 = kb >> 1;
                unsigned a[4];
                a[0] = *(const unsigned*)&Ash[(r0) * 136 + kb + 2 * tg];
                a[1] = *(const unsigned*)&Ash[(r1) * 136 + kb + 2 * tg];
                a[2] = *(const unsigned*)&Ash[(r0) * 136 + kb + 2 * tg + 8];
                a[3] = *(const unsigned*)&Ash[(r1) * 136 + kb + 2 * tg + 8];
#pragma unroll
                for (int nj = 0; nj < 8; nj++) {
                    int n = nj * 8 + g;
                    unsigned bf[2];
                    bf[0] = *(const unsigned*)&vT[swz136w(n, w0 + tg)];
                    bf[1] = *(const unsigned*)&vT[swz136w(n, w0 + tg + 4)];
                    mma_f16(acc[nj], a, bf);
                }
            }
        }
    }

    float qz0 = __shfl_sync(0xffffffffu, acc[8][0], (lane & ~3));
    float qz1 = __shfl_sync(0xffffffffu, acc[8][2], (lane & ~3));
    float inv0 = 1.f / (den0 + qz0 + EPSV);
    float inv1 = 1.f / (den1 + qz1 + EPSV);

#pragma unroll
    for (int nj = 0; nj < 8; nj++) {
        int col = h * 64 + nj * 8 + 2 * tg;
        size_t o0 = ((size_t)b * NSEQ + (size_t)c * CHK + r0) * EE + col;
        size_t o1 = ((size_t)b * NSEQ + (size_t)c * CHK + r1) * EE + col;
        *(__half2*)&out[o0] = __floats2half2_rn(acc[nj][0] * inv0, acc[nj][1] * inv0);
        *(__half2*)&out[o1] = __floats2half2_rn(acc[nj][2] * inv1, acc[nj][3] * inv1);
    }
}

// ---------------------------------------------------------------------------
extern "C" void kernel_launch(void* const* d_in, const int* in_sizes, int n_in,
                              void* d_out, int out_size) {
    const float* Q  = (const float*)d_in[0];
    const float* K  = (const float*)d_in[1];
    const float* V  = (const float*)d_in[2];
    const float* Wq = (const float*)d_in[3];
    const float* Wk = (const float*)d_in[4];
    const float* Wv = (const float*)d_in[5];
    const float* Wo = (const float*)d_in[6];
    const int* causal = (const int*)d_in[7];
    float* out = (float*)d_out;

    __half *qb, *kb, *vb, *ab, *wh, *xh, *Shb, *zhb;
    float *Sb, *zb;
    cudaGetSymbolAddress((void**)&qb, g_q);
    cudaGetSymbolAddress((void**)&kb, g_k);
    cudaGetSymbolAddress((void**)&vb, g_v);
    cudaGetSymbolAddress((void**)&ab, g_attn);
    cudaGetSymbolAddress((void**)&Sb, g_S);
    cudaGetSymbolAddress((void**)&zb, g_z);
    cudaGetSymbolAddress((void**)&Shb, g_Sh);
    cudaGetSymbolAddress((void**)&zhb, g_zh);
    cudaGetSymbolAddress((void**)&wh, g_wh);
    cudaGetSymbolAddress((void**)&xh, g_xh);

    cudaFuncSetAttribute(gemm_h_qkv, cudaFuncAttributeMaxDynamicSharedMemorySize, GSMEM);
    cudaFuncSetAttribute(gemm_h_out, cudaFuncAttributeMaxDynamicSharedMemorySize, GSMEM);
    cudaFuncSetAttribute(chunk_kv_h, cudaFuncAttributeMaxDynamicSharedMemorySize, KV_SMEM);
    cudaFuncSetAttribute(chunk_out_h, cudaFuncAttributeMaxDynamicSharedMemorySize, CO_SMEM);

    conv_all<<<dim3(4096, 7), 256>>>(Wq, Wk, Wv, Wo, Q, K, V, wh, xh);

    dim3 gq(8, 32, 3);
    gemm_h_qkv<<<gq, 256, GSMEM>>>(xh, wh, qb, kb, vb);

    chunk_kv_h<<<BB * HH * NCK, 256, KV_SMEM>>>(kb, vb, Sb, zb);
    prefix_k<<<dim3(BB * HH, 16), 256>>>(Sb, zb, Shb, zhb, causal);
    chunk_out_h<<<BB * HH * NCK, 256, CO_SMEM>>>(qb, kb, vb, Shb, zhb, causal, ab);

    dim3 go(8, 32);
    gemm_h_out<<<go, 256, GSMEM>>>(ab, wh, out);
}

// round 10
// speedup vs baseline: 6.0086x; 1.0594x over previous
#include <cuda_runtime.h>
#include <cuda_fp16.h>
#include <math.h>
#include <stdint.h>

// Problem constants (fixed by setup_inputs)
#define BB    2
#define HH    16
#define NSEQ  2048
#define EE    1024
#define DD    64
#define CHK   128
#define NCK   16
#define EPSV  1e-6f

// fp16 GEMM tiling: 128x128 CTA tile, BK=64 halves, 3-stage cp.async
#define BKH    64
#define SHSTR  72
#define OP_H   (128 * SHSTR)
#define STG_H  (2 * OP_H)
#define STG_B  (STG_H * 2)
#define NSTG   3
#define GSMEM  (NSTG * STG_B)          // 110592 bytes

// chunk_out smem layout (halves)
#define CO_QS   0                      // [128][72]
#define CO_KS   (CO_QS + 128 * 72)     // [128][72]
#define CO_VT   (CO_KS + 128 * 72)     // [64][136] swizzled
#define CO_STZ  (CO_VT + 64 * 136)     // [72][72]
#define CO_AS   (CO_STZ + 72 * 72)     // [128][136]
#define CO_TOT  (CO_AS + 128 * 136)
#define CO_SMEM (CO_TOT * 2)           // 99456 bytes

// chunk_kv smem (halves): kT [64][136] + vT [64][136], swizzled
#define KV_SMEM (2 * 64 * 136 * 2)

// ---------------- scratch (device globals; no allocation allowed) ----------
__device__ __align__(16) __half g_q[BB*HH*NSEQ*DD];
__device__ __align__(16) __half g_k[BB*HH*NSEQ*DD];
__device__ __align__(16) __half g_v[BB*HH*NSEQ*DD];
__device__ __align__(16) __half g_attn[BB*NSEQ*EE];
__device__ float g_S[BB*HH*NCK*DD*DD];                    // per-chunk KtV, [v][d] fp32
__device__ __align__(16) __half g_Sh[BB*HH*NCK*DD*DD];    // prefixed, fp16
__device__ float g_z[BB*HH*NCK*DD];
__device__ __align__(16) __half g_zh[BB*HH*NCK*DD];
__device__ __align__(16) __half g_wh[4 * EE * EE];
__device__ __align__(16) __half g_xh[3 * BB * NSEQ * EE];

// ---------------------------------------------------------------------------
__device__ __forceinline__ void mma_f16(float c[4], const unsigned a[4], const unsigned b[2]) {
    asm volatile(
        "mma.sync.aligned.m16n8k16.row.col.f32.f16.f16.f32 "
        "{%0,%1,%2,%3}, {%4,%5,%6,%7}, {%8,%9}, {%0,%1,%2,%3};\n"
        : "+f"(c[0]), "+f"(c[1]), "+f"(c[2]), "+f"(c[3])
        : "r"(a[0]), "r"(a[1]), "r"(a[2]), "r"(a[3]), "r"(b[0]), "r"(b[1]));
}

__device__ __forceinline__ void ldsm4(unsigned& r0, unsigned& r1,
                                      unsigned& r2, unsigned& r3, uint32_t addr) {
    asm volatile("ldmatrix.sync.aligned.m8n8.x4.shared.b16 {%0,%1,%2,%3}, [%4];"
                 : "=r"(r0), "=r"(r1), "=r"(r2), "=r"(r3) : "r"(addr));
}

__device__ __forceinline__ void cp16s(uint32_t dst, const void* src) {
    asm volatile("cp.async.cg.shared.global [%0], [%1], 16;\n" :: "r"(dst), "l"(src));
}

// swizzled half index into a [64][136] transposed tile: row d, half-col i
__device__ __forceinline__ int swz136(int d, int i) {
    return d * 136 + (((((i >> 1) ^ ((d >> 3) & 7))) << 1) | (i & 1));
}
// word-aligned variant: row d, word wi (2 halves)
__device__ __forceinline__ int swz136w(int d, int wi) {
    return d * 136 + (((wi) ^ ((d >> 3) & 7)) << 1);
}

// ---------------------------------------------------------------------------
// Fused prepass: fp32 -> fp16 for 4 weights (z=0..3) and 3 inputs (z=4..6).
// grid (4096, 7); weights use only first 1024 x-blocks.
// ---------------------------------------------------------------------------
__global__ void __launch_bounds__(256) conv_all(const float* __restrict__ w0,
                                                const float* __restrict__ w1,
                                                const float* __restrict__ w2,
                                                const float* __restrict__ w3,
                                                const float* __restrict__ x0,
                                                const float* __restrict__ x1,
                                                const float* __restrict__ x2,
                                                __half* __restrict__ wdst,
                                                __half* __restrict__ xdst) {
    const int z = blockIdx.y;
    const float* src;
    __half* d;
    if (z < 4) {
        if (blockIdx.x >= 1024) return;
        src = (z == 0) ? w0 : (z == 1) ? w1 : (z == 2) ? w2 : w3;
        d = wdst + (size_t)z * (EE * EE);
    } else {
        src = (z == 4) ? x0 : (z == 5) ? x1 : x2;
        d = xdst + (size_t)(z - 4) * (BB * NSEQ * EE);
    }
    int i = blockIdx.x * 256 + threadIdx.x;
    float4 v = ((const float4*)src)[i];
    __half2 h0 = __floats2half2_rn(v.x, v.y);
    __half2 h1 = __floats2half2_rn(v.z, v.w);
    ((uint2*)d)[i] = make_uint2(*(unsigned*)&h0, *(unsigned*)&h1);
}

// ---------------------------------------------------------------------------
// Pipelined FP16 NT-GEMM with ldmatrix fragment loads.
// ---------------------------------------------------------------------------
template<bool FMAP, bool BHND>
__device__ __forceinline__ void gemm_h_body(const __half* __restrict__ A,
                                            const __half* __restrict__ W,
                                            void* __restrict__ Cv, __half* sm) {
    const int tid = threadIdx.x, lane = tid & 31, warp = tid >> 5;
    const int bm = blockIdx.y * 128, bn = blockIdx.x * 128;
    const int wm = (warp >> 1) * 32, wn = (warp & 1) * 64;
    const int g = lane >> 2, tg = lane & 3;
    const uint32_t sb = (uint32_t)__cvta_generic_to_shared(sm);

    // ldmatrix lane offsets (in halves)
    const int aoff = ((lane & 7) + (lane & 8)) * SHSTR + ((lane & 16) >> 1);
    const int boff = ((lane & 7) + ((lane & 16) >> 1)) * SHSTR + (lane & 8);

    float acc[2][8][4];
#pragma unroll
    for (int mi = 0; mi < 2; mi++)
#pragma unroll
        for (int nj = 0; nj < 8; nj++)
#pragma unroll
            for (int x = 0; x < 4; x++) acc[mi][nj][x] = 0.f;

    auto issue = [&](int buf, int k0) {
        uint32_t dA = sb + buf * STG_B;
        uint32_t dB = dA + OP_H * 2;
#pragma unroll
        for (int i = 0; i < 4; i++) {
            int l = tid + i * 256;
            int r = l >> 3, c8 = (l & 7) * 8;
            uint32_t so = (uint32_t)(r * SHSTR + c8) * 2;
            cp16s(dA + so, A + (size_t)(bm + r) * 1024 + k0 + c8);
            cp16s(dB + so, W + (size_t)(bn + r) * 1024 + k0 + c8);
        }
    };

    issue(0, 0);
    asm volatile("cp.async.commit_group;" ::: "memory");
    issue(1, BKH);
    asm volatile("cp.async.commit_group;" ::: "memory");

    for (int t = 0; t < 16; t++) {
        asm volatile("cp.async.wait_group 1;" ::: "memory");
        __syncthreads();
        if (t + 2 < 16) issue((t + 2) % NSTG, (t + 2) * BKH);
        asm volatile("cp.async.commit_group;" ::: "memory");

        const uint32_t sA = sb + (t % NSTG) * STG_B;
        const uint32_t sB = sA + OP_H * 2;
#pragma unroll
        for (int ks = 0; ks < 4; ks++) {
            const int kb = ks * 16;
            unsigned a[2][4], b[8][2];
#pragma unroll
            for (int mi = 0; mi < 2; mi++) {
                uint32_t ad = sA + (uint32_t)(((wm + mi * 16) * SHSTR + kb) + aoff) * 2;
                ldsm4(a[mi][0], a[mi][1], a[mi][2], a[mi][3], ad);
            }
#pragma unroll
            for (int p = 0; p < 4; p++) {
                uint32_t bd = sB + (uint32_t)(((wn + p * 16) * SHSTR + kb) + boff) * 2;
                ldsm4(b[2*p][0], b[2*p][1], b[2*p+1][0], b[2*p+1][1], bd);
            }
#pragma unroll
            for (int mi = 0; mi < 2; mi++)
#pragma unroll
                for (int nj = 0; nj < 8; nj++)
                    mma_f16(acc[mi][nj], a[mi], b[nj]);
        }
    }

#pragma unroll
    for (int mi = 0; mi < 2; mi++) {
#pragma unroll
        for (int nj = 0; nj < 8; nj++) {
            int row0 = bm + wm + mi * 16 + g;
            int col0 = bn + wn + nj * 8 + 2 * tg;
#pragma unroll
            for (int half_ = 0; half_ < 2; half_++) {
                int row = row0 + half_ * 8;
                float v0 = acc[mi][nj][half_ * 2 + 0];
                float v1 = acc[mi][nj][half_ * 2 + 1];
                if (FMAP) {
                    v0 = (v0 > 0.f) ? (v0 + 1.f) : expf(v0);
                    v1 = (v1 > 0.f) ? (v1 + 1.f) : expf(v1);
                }
                if (BHND) {
                    int bb = row >> 11, n = row & 2047;
                    int h = col0 >> 6, d = col0 & 63;
                    size_t idx = ((((size_t)bb * HH + h) * NSEQ + n) * DD + d);
                    __half2 hv = __floats2half2_rn(v0, v1);
                    *(__half2*)&((__half*)Cv)[idx] = hv;
                } else {
                    size_t idx = (size_t)row * 1024 + col0;
                    *(float2*)&((float*)Cv)[idx] = make_float2(v0, v1);
                }
            }
        }
    }
}

__global__ void __launch_bounds__(256, 2) gemm_h_qkv(const __half* __restrict__ XH,
                                                     const __half* __restrict__ WH,
                                                     __half* __restrict__ qb,
                                                     __half* __restrict__ kb,
                                                     __half* __restrict__ vb) {
    extern __shared__ __half smh[];
    const int z = blockIdx.z;
    const __half* A = XH + (size_t)z * (BB * NSEQ * EE);
    const __half* W = WH + (size_t)z * (EE * EE);
    __half* C = (z == 0) ? qb : (z == 1) ? kb : vb;
    if (z < 2) gemm_h_body<true,  true>(A, W, C, smh);
    else       gemm_h_body<false, true>(A, W, C, smh);
}

__global__ void __launch_bounds__(256, 2) gemm_h_out(const __half* __restrict__ A,
                                                     const __half* __restrict__ WH,
                                                     float* __restrict__ C) {
    extern __shared__ __half smh[];
    gemm_h_body<false, false>(A, WH + (size_t)3 * EE * EE, C, smh);
}

// ---------------------------------------------------------------------------
// Pass 1 (fp16 mma): ST_c[v][d] = sum_i k[i,d]*v[i,v] (fp32, transposed),
// z_c[d] = sum_i k[i,d]. Swizzled smem transposes (conflict-free).
// ---------------------------------------------------------------------------
__global__ void __launch_bounds__(256) chunk_kv_h(const __half* __restrict__ k,
                                                  const __half* __restrict__ v,
                                                  float* __restrict__ S,
                                                  float* __restrict__ z) {
    extern __shared__ __half smh[];
    __half* kT = smh;              // [64][136] swizzled
    __half* vT = smh + 64 * 136;
    const int blk = blockIdx.x;
    const int c = blk & 15, bh = blk >> 4;
    const int tid = threadIdx.x;
    const int lane = tid & 31, warp = tid >> 5;
    const int g = lane >> 2, tg = lane & 3;

    const size_t base = ((size_t)bh * NSEQ + (size_t)c * CHK) * DD;
    for (int idx = tid; idx < 1024; idx += 256) {
        int i = idx >> 3, d8 = (idx & 7) * 8;
        uint4 kk = *(const uint4*)&k[base + (size_t)i * 64 + d8];
        uint4 vv = *(const uint4*)&v[base + (size_t)i * 64 + d8];
        const __half* kh = (const __half*)&kk;
        const __half* vh = (const __half*)&vv;
#pragma unroll
        for (int j = 0; j < 8; j++) {
            kT[swz136(d8 + j, i)] = kh[j];
            vT[swz136(d8 + j, i)] = vh[j];
        }
    }
    __syncthreads();

    // z: 4 lanes per d, word loads
    {
        int d = tid >> 2, quad = tid & 3;
        float s = 0.f;
#pragma unroll
        for (int wi = 0; wi < 16; wi++) {
            unsigned u = *(const unsigned*)&kT[swz136w(d, quad * 16 + wi)];
            __half2 h = *(__half2*)&u;
            s += __half2float(h.x) + __half2float(h.y);
        }
        s += __shfl_xor_sync(0xffffffffu, s, 1);
        s += __shfl_xor_sync(0xffffffffu, s, 2);
        if (quad == 0) z[(size_t)blk * 64 + d] = s;
    }

    const int wm = (warp & 1) * 32, wn = (warp >> 1) * 16;
    float acc[2][2][4];
#pragma unroll
    for (int mi = 0; mi < 2; mi++)
#pragma unroll
        for (int nj = 0; nj < 2; nj++)
#pragma unroll
            for (int x = 0; x < 4; x++) acc[mi][nj][x] = 0.f;

#pragma unroll
    for (int kb = 0; kb < 128; kb += 16) {
        const int w0 = kb >> 1;    // word base
        unsigned a[2][4], b[2][2];
#pragma unroll
        for (int mi = 0; mi < 2; mi++) {
            int m = wm + mi * 16 + g;
            a[mi][0] = *(const unsigned*)&kT[swz136w(m,     w0 + tg)];
            a[mi][1] = *(const unsigned*)&kT[swz136w(m + 8, w0 + tg)];
            a[mi][2] = *(const unsigned*)&kT[swz136w(m,     w0 + tg + 4)];
            a[mi][3] = *(const unsigned*)&kT[swz136w(m + 8, w0 + tg + 4)];
        }
#pragma unroll
        for (int nj = 0; nj < 2; nj++) {
            int n = wn + nj * 8 + g;
            b[nj][0] = *(const unsigned*)&vT[swz136w(n, w0 + tg)];
            b[nj][1] = *(const unsigned*)&vT[swz136w(n, w0 + tg + 4)];
        }
#pragma unroll
        for (int mi = 0; mi < 2; mi++)
#pragma unroll
            for (int nj = 0; nj < 2; nj++)
                mma_f16(acc[mi][nj], a[mi], b[nj]);
    }

    float* Sc = S + (size_t)blk * 4096;
#pragma unroll
    for (int mi = 0; mi < 2; mi++) {
#pragma unroll
        for (int nj = 0; nj < 2; nj++) {
            int d0 = wm + mi * 16 + g;
            int v0 = wn + nj * 8 + 2 * tg;
            Sc[(v0)     * 64 + d0    ] = acc[mi][nj][0];
            Sc[(v0 + 1) * 64 + d0    ] = acc[mi][nj][1];
            Sc[(v0)     * 64 + d0 + 8] = acc[mi][nj][2];
            Sc[(v0 + 1) * 64 + d0 + 8] = acc[mi][nj][3];
        }
    }
}

// ---------------------------------------------------------------------------
// Pass 2: exclusive prefix (causal) / total (non-causal); fp32 scan in regs,
// fp16 output for chunk_out. grid (32,16).
// ---------------------------------------------------------------------------
__global__ void __launch_bounds__(256) prefix_k(const float* __restrict__ S,
                                                const float* __restrict__ z,
                                                __half* __restrict__ Sh,
                                                __half* __restrict__ zh,
                                                const int* __restrict__ causal) {
    const int bh = blockIdx.x;
    const int e = blockIdx.y * 256 + threadIdx.x;
    const int caus = *causal;
    {
        float run = 0.f;
        if (caus) {
            for (int c = 0; c < NCK; c++) {
                size_t idx = ((size_t)bh * NCK + c) * 4096 + e;
                Sh[idx] = __float2half_rn(run);
                run += S[idx];
            }
        } else {
            for (int c = 0; c < NCK; c++) run += S[((size_t)bh * NCK + c) * 4096 + e];
            __half hr = __float2half_rn(run);
            for (int c = 0; c < NCK; c++) Sh[((size_t)bh * NCK + c) * 4096 + e] = hr;
        }
    }
    if (blockIdx.y == 0 && threadIdx.x < 64) {
        int d = threadIdx.x;
        float run = 0.f;
        if (caus) {
            for (int c = 0; c < NCK; c++) {
                size_t idx = ((size_t)bh * NCK + c) * 64 + d;
                zh[idx] = __float2half_rn(run);
                run += z[idx];
            }
        } else {
            for (int c = 0; c < NCK; c++) run += z[((size_t)bh * NCK + c) * 64 + d];
            __half hr = __float2half_rn(run);
            for (int c = 0; c < NCK; c++) zh[((size_t)bh * NCK + c) * 64 + d] = hr;
        }
    }
}

// ---------------------------------------------------------------------------
// Pass 3 (fp16 mma): per-chunk output. Triangular skips + swizzled vT.
// ---------------------------------------------------------------------------
__global__ void __launch_bounds__(256) chunk_out_h(const __half* __restrict__ q,
                                                   const __half* __restrict__ k,
                                                   const __half* __restrict__ v,
                                                   const __half* __restrict__ Sh,
                                                   const __half* __restrict__ zh,
                                                   const int* __restrict__ causal,
                                                   __half* __restrict__ out) {
    extern __shared__ __half smh[];
    __half* qs  = smh + CO_QS;    // [128][72]
    __half* ks  = smh + CO_KS;    // [128][72]
    __half* vT  = smh + CO_VT;    // [64][136] swizzled
    __half* STz = smh + CO_STZ;   // [72][72]
    __half* Ash = smh + CO_AS;    // [128][136]

    const int blk = blockIdx.x;
    const int c = blk & 15, bh = blk >> 4;
    const int b = bh >> 4, h = bh & 15;
    const int tid = threadIdx.x;
    const int lane = tid & 31, warp = tid >> 5;
    const int g = lane >> 2, tg = lane & 3;
    const int caus = *causal;
    const int m0 = warp * 16;

    const size_t base = ((size_t)bh * NSEQ + (size_t)c * CHK) * DD;
    for (int idx = tid; idx < 1024; idx += 256) {
        int i = idx >> 3, d8 = (idx & 7) * 8;
        *(uint4*)&qs[i * 72 + d8] = *(const uint4*)&q[base + (size_t)i * 64 + d8];
        *(uint4*)&ks[i * 72 + d8] = *(const uint4*)&k[base + (size_t)i * 64 + d8];
        uint4 vv = *(const uint4*)&v[base + (size_t)i * 64 + d8];
        const __half* vh = (const __half*)&vv;
#pragma unroll
        for (int j = 0; j < 8; j++) vT[swz136(d8 + j, i)] = vh[j];
    }
    // STz rows 0-63 = S^T (fp16 in global already)
    for (int idx = tid; idx < 512; idx += 256) {
        int j = idx >> 3, d8 = (idx & 7) * 8;
        *(uint4*)&STz[j * 72 + d8] =
            *(const uint4*)&Sh[(size_t)blk * 4096 + (size_t)j * 64 + d8];
    }
    if (tid < 64) STz[64 * 72 + tid] = zh[(size_t)blk * 64 + tid];
    for (int idx = tid; idx < 7 * 72; idx += 256) STz[65 * 72 + idx] = __float2half_rn(0.f);
    __syncthreads();

    const int r0 = m0 + g, r1 = r0 + 8;
    float den0 = 0.f, den1 = 0.f;

    if (caus) {
        const int njmax = 2 * warp + 1;    // tiles nj > njmax are all-zero
#pragma unroll
        for (int h2 = 0; h2 < 2; h2++) {
            if (h2 * 8 <= njmax) {
                float accA[8][4];
#pragma unroll
                for (int nj = 0; nj < 8; nj++)
#pragma unroll
                    for (int x = 0; x < 4; x++) accA[nj][x] = 0.f;
#pragma unroll
                for (int kb = 0; kb < 64; kb += 16) {
                    unsigned a[4];
                    a[0] = *(const unsigned*)&qs[(r0) * 72 + kb + 2 * tg];
                    a[1] = *(const unsigned*)&qs[(r1) * 72 + kb + 2 * tg];
                    a[2] = *(const unsigned*)&qs[(r0) * 72 + kb + 2 * tg + 8];
                    a[3] = *(const unsigned*)&qs[(r1) * 72 + kb + 2 * tg + 8];
#pragma unroll
                    for (int nj = 0; nj < 8; nj++) {
                        int njg = h2 * 8 + nj;
                        if (njg <= njmax) {
                            unsigned bf[2];
                            bf[0] = *(const unsigned*)&ks[(njg * 8 + g) * 72 + kb + 2 * tg];
                            bf[1] = *(const unsigned*)&ks[(njg * 8 + g) * 72 + kb + 2 * tg + 8];
                            mma_f16(accA[nj], a, bf);
                        }
                    }
                }
#pragma unroll
                for (int nj = 0; nj < 8; nj++) {
                    int njg = h2 * 8 + nj;
                    if (njg <= njmax) {
                        int c0 = njg * 8 + 2 * tg;
                        float x00 = (c0     <= r0) ? accA[nj][0] : 0.f;
                        float x01 = (c0 + 1 <= r0) ? accA[nj][1] : 0.f;
                        float x10 = (c0     <= r1) ? accA[nj][2] : 0.f;
                        float x11 = (c0 + 1 <= r1) ? accA[nj][3] : 0.f;
                        den0 += x00 + x01;
                        den1 += x10 + x11;
                        *(__half2*)&Ash[r0 * 136 + c0] = __floats2half2_rn(x00, x01);
                        *(__half2*)&Ash[r1 * 136 + c0] = __floats2half2_rn(x10, x11);
                    }
                }
            }
        }
        den0 += __shfl_xor_sync(0xffffffffu, den0, 1);
        den0 += __shfl_xor_sync(0xffffffffu, den0, 2);
        den1 += __shfl_xor_sync(0xffffffffu, den1, 1);
        den1 += __shfl_xor_sync(0xffffffffu, den1, 2);
        __syncwarp();   // Ash rows are warp-private
    }

    float acc[9][4];
#pragma unroll
    for (int nj = 0; nj < 9; nj++)
#pragma unroll
        for (int x = 0; x < 4; x++) acc[nj][x] = 0.f;

    // q · [S^T | z]  (k-dim = 64)
#pragma unroll
    for (int kb = 0; kb < 64; kb += 16) {
        unsigned a[4];
        a[0] = *(const unsigned*)&qs[(r0) * 72 + kb + 2 * tg];
        a[1] = *(const unsigned*)&qs[(r1) * 72 + kb + 2 * tg];
        a[2] = *(const unsigned*)&qs[(r0) * 72 + kb + 2 * tg + 8];
        a[3] = *(const unsigned*)&qs[(r1) * 72 + kb + 2 * tg + 8];
#pragma unroll
        for (int nj = 0; nj < 9; nj++) {
            unsigned bf[2];
            bf[0] = *(const unsigned*)&STz[(nj * 8 + g) * 72 + kb + 2 * tg];
            bf[1] = *(const unsigned*)&STz[(nj * 8 + g) * 72 + kb + 2 * tg + 8];
            mma_f16(acc[nj], a, bf);
        }
    }
    // A · v  (k-dim = 128): A cols > m0+15 are zero -> only k-tiles kb/16 <= warp
    if (caus) {
#pragma unroll
        for (int kb = 0; kb < 128; kb += 16) {
            if ((kb >> 4) <= warp) {
                const int w0 = kb >> 1;
                unsigned a[4];
                a[0] = *(const unsigned*)&Ash[(r0) * 136 + kb + 2 * tg];
                a[1] = *(const unsigned*)&Ash[(r1) * 136 + kb + 2 * tg];
                a[2] = *(const unsigned*)&Ash[(r0) * 136 + kb + 2 * tg + 8];
                a[3] = *(const unsigned*)&Ash[(r1) * 136 + kb + 2 * tg + 8];
#pragma unroll
                for (int nj = 0; nj < 8; nj++) {
                    int n = nj * 8 + g;
                    unsigned bf[2];
                    bf[0] = *(const unsigned*)&vT[swz136w(n, w0 + tg)];
                    bf[1] = *(const unsigned*)&vT[swz136w(n, w0 + tg + 4)];
                    mma_f16(acc[nj], a, bf);
                }
            }
        }
    }

    float qz0 = __shfl_sync(0xffffffffu, acc[8][0], (lane & ~3));
    float qz1 = __shfl_sync(0xffffffffu, acc[8][2], (lane & ~3));
    float inv0 = 1.f / (den0 + qz0 + EPSV);
    float inv1 = 1.f / (den1 + qz1 + EPSV);

#pragma unroll
    for (int nj = 0; nj < 8; nj++) {
        int col = h * 64 + nj * 8 + 2 * tg;
        size_t o0 = ((size_t)b * NSEQ + (size_t)c * CHK + r0) * EE + col;
        size_t o1 = ((size_t)b * NSEQ + (size_t)c * CHK + r1) * EE + col;
        *(__half2*)&out[o0] = __floats2half2_rn(acc[nj][0] * inv0, acc[nj][1] * inv0);
        *(__half2*)&out[o1] = __floats2half2_rn(acc[nj][2] * inv1, acc[nj][3] * inv1);
    }
}

// ---------------------------------------------------------------------------
extern "C" void kernel_launch(void* const* d_in, const int* in_sizes, int n_in,
                              void* d_out, int out_size) {
    const float* Q  = (const float*)d_in[0];
    const float* K  = (const float*)d_in[1];
    const float* V  = (const float*)d_in[2];
    const float* Wq = (const float*)d_in[3];
    const float* Wk = (const float*)d_in[4];
    const float* Wv = (const float*)d_in[5];
    const float* Wo = (const float*)d_in[6];
    const int* causal = (const int*)d_in[7];
    float* out = (float*)d_out;

    __half *qb, *kb, *vb, *ab, *wh, *xh, *Shb, *zhb;
    float *Sb, *zb;
    cudaGetSymbolAddress((void**)&qb, g_q);
    cudaGetSymbolAddress((void**)&kb, g_k);
    cudaGetSymbolAddress((void**)&vb, g_v);
    cudaGetSymbolAddress((void**)&ab, g_attn);
    cudaGetSymbolAddress((void**)&Sb, g_S);
    cudaGetSymbolAddress((void**)&zb, g_z);
    cudaGetSymbolAddress((void**)&Shb, g_Sh);
    cudaGetSymbolAddress((void**)&zhb, g_zh);
    cudaGetSymbolAddress((void**)&wh, g_wh);
    cudaGetSymbolAddress((void**)&xh, g_xh);

    cudaFuncSetAttribute(gemm_h_qkv, cudaFuncAttributeMaxDynamicSharedMemorySize, GSMEM);
    cudaFuncSetAttribute(gemm_h_out, cudaFuncAttributeMaxDynamicSharedMemorySize, GSMEM);
    cudaFuncSetAttribute(chunk_kv_h, cudaFuncAttributeMaxDynamicSharedMemorySize, KV_SMEM);
    cudaFuncSetAttribute(chunk_out_h, cudaFuncAttributeMaxDynamicSharedMemorySize, CO_SMEM);

    conv_all<<<dim3(4096, 7), 256>>>(Wq, Wk, Wv, Wo, Q, K, V, wh, xh);

    dim3 gq(8, 32, 3);
    gemm_h_qkv<<<gq, 256, GSMEM>>>(xh, wh, qb, kb, vb);

    chunk_kv_h<<<BB * HH * NCK, 256, KV_SMEM>>>(kb, vb, Sb, zb);
    prefix_k<<<dim3(BB * HH, 16), 256>>>(Sb, zb, Shb, zhb, causal);
    chunk_out_h<<<BB * HH * NCK, 256, CO_SMEM>>>(qb, kb, vb, Shb, zhb, causal, ab);

    dim3 go(8, 32);
    gemm_h_out<<<go, 256, GSMEM>>>(ab, wh, out);
}